// round 7
// baseline (speedup 1.0000x reference)
#include <cuda_runtime.h>
#include <cstdint>

#define NA 261888
#define TOPK 1000
#define POST 300

// ---------------- static scratch (no allocations allowed) ----------------
// Per-level conv outputs (2 batches x 256 ch x HW), levels p2..p6 back-to-back.
__device__ float              g_x[(size_t)44695552];
__device__ float              g_scores[2 * NA];
__device__ float4             g_boxes[2 * NA];
__device__ unsigned           g_hist[2][65536];
__device__ unsigned           g_selHi[2];
__device__ unsigned           g_above[2];
__device__ unsigned           g_T[2];
__device__ int                g_candCnt[2];
__device__ unsigned long long g_cand[2][2048];
__device__ float              g_ts[2][1024];
__device__ float4             g_tb[2][1024];

// ---------------- f32x2 packed-FMA helpers (Blackwell) ----------------
__device__ __forceinline__ unsigned long long pack_dup(float v) {
    unsigned long long r;
    unsigned u = __float_as_uint(v);
    asm("mov.b64 %0, {%1, %1};" : "=l"(r) : "r"(u));
    return r;
}
__device__ __forceinline__ void fma2(unsigned long long& acc,
                                     unsigned long long a,
                                     unsigned long long b) {
    asm("fma.rn.f32x2 %0, %1, %2, %0;" : "+l"(acc) : "l"(a), "l"(b));
}
__device__ __forceinline__ void unpack2(unsigned long long v, float& lo, float& hi) {
    unsigned a, b;
    asm("mov.b64 {%0, %1}, %2;" : "=r"(a), "=r"(b) : "l"(v));
    lo = __uint_as_float(a);
    hi = __uint_as_float(b);
}

// ---------------- XLA-exact sigmoid: 0.5 + 0.5*fast_tanh(0.5*x) ----------------
__device__ __forceinline__ float xla_fast_tanh(float x) {
    const float kBound = 7.90531110763549805f;
    float xc = fminf(fmaxf(x, -kBound), kBound);
    float x2 = __fmul_rn(xc, xc);
    float n = __fadd_rn(__fmul_rn(x2, -2.76076847742355e-16f), 2.00018790482477e-13f);
    n = __fadd_rn(__fmul_rn(x2, n), -8.60467152213735e-11f);
    n = __fadd_rn(__fmul_rn(x2, n),  5.12229709037114e-08f);
    n = __fadd_rn(__fmul_rn(x2, n),  1.48572235717979e-05f);
    n = __fadd_rn(__fmul_rn(x2, n),  6.37261928875436e-04f);
    n = __fadd_rn(__fmul_rn(x2, n),  4.89352455891786e-03f);
    n = __fmul_rn(xc, n);
    float d = __fadd_rn(__fmul_rn(x2, 1.19825839466702e-06f), 1.18534705686654e-04f);
    d = __fadd_rn(__fmul_rn(x2, d), 2.26843463243900e-03f);
    d = __fadd_rn(__fmul_rn(x2, d), 4.89352518554385e-03f);
    float t = __fdiv_rn(n, d);
    return (fabsf(x) < 0.0004f) ? x : t;
}
__device__ __forceinline__ float xla_sigmoid(float l) {
    float t = xla_fast_tanh(__fmul_rn(0.5f, l));
    return __fadd_rn(0.5f, __fmul_rn(0.5f, t));
}

// ---------------- conv 3x3 (256->256) + bias + relu ----------------
// Tile 2 rows x 64 cols x 64 oc, 256 threads. Same per-output FMA chain order
// (ic asc, ky asc, kx asc) as rounds 4-6 -> bitwise-identical output.
// NEW: double-buffered dynamic smem; stage icb+1 while computing icb; one
// __syncthreads per icb.
#define IN2_STRIDE 2112            // 8*4*66 ULL per buffer
#define W_STRIDE   4896            // 8*9*68 floats per buffer
#define CONV_SMEM  (2 * IN2_STRIDE * 8 + 2 * W_STRIDE * 4)   // 72960 bytes

__global__ void __launch_bounds__(256, 2)
conv3x3_relu_kernel(const float* __restrict__ in,
                    const float* __restrict__ w,
                    const float* __restrict__ bias,
                    float* __restrict__ xout,
                    int H, int W) {
    extern __shared__ char dynsmem[];
    unsigned long long* s_in2 = reinterpret_cast<unsigned long long*>(dynsmem);
    float* s_w = reinterpret_cast<float*>(dynsmem + 2 * IN2_STRIDE * 8);

    const int tx  = threadIdx.x & 31;
    const int ty  = threadIdx.x >> 5;
    const int x0  = blockIdx.x * 64;
    const int y0  = blockIdx.y * 2;
    const int b   = blockIdx.z >> 2;
    const int ocb = (blockIdx.z & 3) * 64;

    unsigned long long acc2[4][4];
#pragma unroll
    for (int i = 0; i < 4; i++)
#pragma unroll
        for (int j = 0; j < 4; j++) acc2[i][j] = 0ULL;

    const float* inB = in + (size_t)b * 256 * H * W;

    // ---- stage helper (macro-ish lambda): fills buffer `bi` with slice icb ----
    auto stage = [&](int bi, int icb) {
        unsigned long long* din = s_in2 + bi * IN2_STRIDE;
        float* dw = s_w + bi * W_STRIDE;
        for (int e = threadIdx.x; e < 8 * 4 * 66; e += 256) {
            int ic = e / 264; int rem = e % 264; int r = rem / 66; int c = rem % 66;
            int yy = y0 + r - 1; int xx = x0 + c - 1;
            float v = 0.f;
            if (yy >= 0 && yy < H && xx >= 0 && xx < W)
                v = inB[(size_t)(icb + ic) * H * W + (size_t)yy * W + xx];
            din[ic * 264 + r * 66 + c] = pack_dup(v);
        }
        for (int e = threadIdx.x; e < 8 * 64 * 9; e += 256) {
            int oc = e / 72; int rem = e % 72; int ic = rem / 9; int k = rem % 9;
            dw[ic * 612 + k * 68 + oc] = w[((size_t)(ocb + oc) * 256 + (size_t)(icb + ic)) * 9 + k];
        }
    };

    stage(0, 0);
    __syncthreads();

    for (int icb = 0; icb < 256; icb += 8) {
        const int cur = (icb >> 3) & 1;
        if (icb + 8 < 256) stage(cur ^ 1, icb + 8);   // overlap next-slice loads

        const unsigned long long* bin = s_in2 + cur * IN2_STRIDE;
        const float* bw = s_w + cur * W_STRIDE;
#pragma unroll
        for (int ic = 0; ic < 8; ic++) {
            unsigned long long pa[4][3], pb[4][3];
#pragma unroll
            for (int r = 0; r < 4; r++)
#pragma unroll
                for (int c = 0; c < 3; c++) {
                    pa[r][c] = bin[ic * 264 + r * 66 + tx + c];
                    pb[r][c] = bin[ic * 264 + r * 66 + tx + 32 + c];
                }
#pragma unroll
            for (int k = 0; k < 9; k++) {
                const int ky = k / 3, kx = k % 3;
                ulonglong2 wv0 = *reinterpret_cast<const ulonglong2*>(&bw[ic * 612 + k * 68 + 8 * ty]);
                ulonglong2 wv1 = *reinterpret_cast<const ulonglong2*>(&bw[ic * 612 + k * 68 + 8 * ty + 4]);
                fma2(acc2[0][0], pa[ky][kx],     wv0.x);
                fma2(acc2[0][1], pb[ky][kx],     wv0.x);
                fma2(acc2[0][2], pa[ky + 1][kx], wv0.x);
                fma2(acc2[0][3], pb[ky + 1][kx], wv0.x);
                fma2(acc2[1][0], pa[ky][kx],     wv0.y);
                fma2(acc2[1][1], pb[ky][kx],     wv0.y);
                fma2(acc2[1][2], pa[ky + 1][kx], wv0.y);
                fma2(acc2[1][3], pb[ky + 1][kx], wv0.y);
                fma2(acc2[2][0], pa[ky][kx],     wv1.x);
                fma2(acc2[2][1], pb[ky][kx],     wv1.x);
                fma2(acc2[2][2], pa[ky + 1][kx], wv1.x);
                fma2(acc2[2][3], pb[ky + 1][kx], wv1.x);
                fma2(acc2[3][0], pa[ky][kx],     wv1.y);
                fma2(acc2[3][1], pb[ky][kx],     wv1.y);
                fma2(acc2[3][2], pa[ky + 1][kx], wv1.y);
                fma2(acc2[3][3], pb[ky + 1][kx], wv1.y);
            }
        }
        __syncthreads();   // one barrier per icb: protects both buffers
    }

#pragma unroll
    for (int op = 0; op < 4; op++) {
        const int ocl = ocb + 8 * ty + 2 * op;
        const float bv0 = bias[ocl];
        const float bv1 = bias[ocl + 1];
        float* out0 = xout + (size_t)(b * 256 + ocl) * H * W;
        float* out1 = out0 + (size_t)H * W;
#pragma unroll
        for (int q = 0; q < 4; q++) {
            float v0, v1;
            unpack2(acc2[op][q], v0, v1);
            int y = y0 + (q >> 1);
            int x = (q & 1) ? (x0 + 32 + tx) : (x0 + tx);
            if (x < W) {
                out0[(size_t)y * W + x] = fmaxf(__fadd_rn(v0, bv0), 0.f);
                out1[(size_t)y * W + x] = fmaxf(__fadd_rn(v1, bv1), 0.f);
            }
        }
    }
}

// ---------------- 1x1 heads + anchor decode + sigmoid + mask ----------------
// (round-5 version: 1 pixel/thread — best measured; per-pixel c-ascending order)
__global__ void head_decode_kernel(const float* __restrict__ clsw, const float* __restrict__ clsb,
                                   const float* __restrict__ boxw, const float* __restrict__ boxb,
                                   const float* __restrict__ xin,
                                   int H, int W, int stride, float asize, int lvl_off) {
    __shared__ float s_cw[3 * 256];
    __shared__ float s_bw[12 * 256];
    for (int e = threadIdx.x; e < 3 * 256; e += blockDim.x) s_cw[e] = clsw[e];
    for (int e = threadIdx.x; e < 12 * 256; e += blockDim.x) s_bw[e] = boxw[e];
    __syncthreads();

    int pix = blockIdx.x * blockDim.x + threadIdx.x;
    int b   = blockIdx.y;
    int HW  = H * W;
    if (pix >= HW) return;

    const float* xp = xin + (size_t)b * 256 * HW + pix;
    float o[3]  = {0.f, 0.f, 0.f};
    float d[12];
#pragma unroll
    for (int j = 0; j < 12; j++) d[j] = 0.f;

    for (int c = 0; c < 256; c++) {
        float v = xp[(size_t)c * HW];
        o[0] += v * s_cw[c];
        o[1] += v * s_cw[256 + c];
        o[2] += v * s_cw[512 + c];
#pragma unroll
        for (int j = 0; j < 12; j++) d[j] += v * s_bw[j * 256 + c];
    }
#pragma unroll
    for (int a = 0; a < 3; a++) o[a] = __fadd_rn(o[a], clsb[a]);
#pragma unroll
    for (int j = 0; j < 12; j++) d[j] = __fadd_rn(d[j], boxb[j]);

    int yy = pix / W, xx = pix % W;
    float xs = (float)(xx * stride), ys = (float)(yy * stride);
    const float ratios[3] = {0.5f, 1.0f, 2.0f};
#pragma unroll
    for (int a = 0; a < 3; a++) {
        float s  = sqrtf(ratios[a]);
        float hh = __fmul_rn(asize, s);
        float ww = __fdiv_rn(asize, s);
        float ax1 = __fadd_rn(xs, -0.5f * ww);
        float ax2 = __fadd_rn(xs,  0.5f * ww);
        float ay1 = __fadd_rn(ys, -0.5f * hh);
        float ay2 = __fadd_rn(ys,  0.5f * hh);
        float aw = __fsub_rn(ax2, ax1);
        float ah = __fsub_rn(ay2, ay1);
        float ax = __fadd_rn(ax1, 0.5f * aw);
        float ay = __fadd_rn(ay1, 0.5f * ah);
        float dx = d[4 * a], dy = d[4 * a + 1], dw = d[4 * a + 2], dh = d[4 * a + 3];
        float cx = __fadd_rn(__fmul_rn(dx, aw), ax);
        float cy = __fadd_rn(__fmul_rn(dy, ah), ay);
        float pw = __fmul_rn(expf(dw), aw);
        float ph = __fmul_rn(expf(dh), ah);
        float x1 = __fsub_rn(cx, 0.5f * pw);
        float y1 = __fsub_rn(cy, 0.5f * ph);
        float x2 = __fadd_rn(cx, 0.5f * pw);
        float y2 = __fadd_rn(cy, 0.5f * ph);
        x1 = fminf(fmaxf(x1, 0.f), 1024.f);
        y1 = fminf(fmaxf(y1, 0.f), 1024.f);
        x2 = fminf(fmaxf(x2, 0.f), 1024.f);
        y2 = fminf(fmaxf(y2, 0.f), 1024.f);
        float ws = __fsub_rn(x2, x1), hs = __fsub_rn(y2, y1);
        bool valid = (ws >= 1.0f) && (hs >= 1.0f);
        float sc = xla_sigmoid(o[a]);
        float masked = valid ? sc : -1e9f;
        int aidx = lvl_off + pix * 3 + a;
        g_scores[(size_t)b * NA + aidx] = masked;
        g_boxes[(size_t)b * NA + aidx] = make_float4(x1, y1, x2, y2);
    }
}

// ---------------- top-k via 2-pass 16-bit radix select ----------------
__device__ __forceinline__ unsigned f2u(float f) {
    unsigned u = __float_as_uint(f);
    return (u & 0x80000000u) ? ~u : (u | 0x80000000u);
}

__global__ void zero_hist_kernel() {
    int i = blockIdx.x * blockDim.x + threadIdx.x;
    if (i < 2 * 65536) (&g_hist[0][0])[i] = 0u;
}

__global__ void hist_hi_kernel() {
    for (int i = blockIdx.x * blockDim.x + threadIdx.x; i < 2 * NA; i += gridDim.x * blockDim.x) {
        int b = i / NA;
        unsigned k = f2u(g_scores[i]);
        atomicAdd(&g_hist[b][k >> 16], 1u);
    }
}

__global__ void scan_hi_kernel() {
    int b = blockIdx.x, tid = threadIdx.x;
    __shared__ unsigned ssum[1024];
    unsigned tsum = 0;
    int base = tid * 64;
    for (int i = 0; i < 64; i++) tsum += g_hist[b][base + i];
    ssum[tid] = tsum;
    __syncthreads();
    for (int off = 1; off < 1024; off <<= 1) {
        unsigned v = (tid + off < 1024) ? ssum[tid + off] : 0u;
        __syncthreads();
        ssum[tid] += v;
        __syncthreads();
    }
    unsigned above = ssum[tid] - tsum;
    if (above < TOPK && above + tsum >= TOPK) {
        unsigned acc = above;
        for (int i = 63; i >= 0; i--) {
            unsigned c = g_hist[b][base + i];
            if (acc + c >= TOPK) { g_selHi[b] = (unsigned)(base + i); g_above[b] = acc; break; }
            acc += c;
        }
    }
}

__global__ void hist_lo_kernel() {
    for (int i = blockIdx.x * blockDim.x + threadIdx.x; i < 2 * NA; i += gridDim.x * blockDim.x) {
        int b = i / NA;
        unsigned k = f2u(g_scores[i]);
        if ((k >> 16) == g_selHi[b]) atomicAdd(&g_hist[b][k & 0xFFFFu], 1u);
    }
}

__global__ void scan_lo_kernel() {
    int b = blockIdx.x, tid = threadIdx.x;
    unsigned Kp = TOPK - g_above[b];
    __shared__ unsigned ssum[1024];
    unsigned tsum = 0;
    int base = tid * 64;
    for (int i = 0; i < 64; i++) tsum += g_hist[b][base + i];
    ssum[tid] = tsum;
    __syncthreads();
    for (int off = 1; off < 1024; off <<= 1) {
        unsigned v = (tid + off < 1024) ? ssum[tid + off] : 0u;
        __syncthreads();
        ssum[tid] += v;
        __syncthreads();
    }
    unsigned above = ssum[tid] - tsum;
    if (above < Kp && above + tsum >= Kp) {
        unsigned acc = above;
        for (int i = 63; i >= 0; i--) {
            unsigned c = g_hist[b][base + i];
            if (acc + c >= Kp) {
                g_T[b] = (g_selHi[b] << 16) | (unsigned)(base + i);
                break;
            }
            acc += c;
        }
    }
    if (tid == 0) g_candCnt[b] = 0;
}

__global__ void compact_kernel() {
    for (int i = blockIdx.x * blockDim.x + threadIdx.x; i < 2 * NA; i += gridDim.x * blockDim.x) {
        int b = i / NA;
        unsigned k = f2u(g_scores[i]);
        if (k >= g_T[b]) {
            int p = atomicAdd(&g_candCnt[b], 1);
            if (p < 2048) {
                unsigned idx = (unsigned)(i - b * NA);
                g_cand[b][p] = ((unsigned long long)k << 32) | (unsigned long long)(~idx);
            }
        }
    }
}

// Bitonic sort of <=2048 candidates, composite key (score desc, index asc)
__global__ void sort_topk_kernel() {
    int b = blockIdx.x, tid = threadIdx.x;
    __shared__ unsigned long long s[2048];
    int n = g_candCnt[b];
    if (n > 2048) n = 2048;
    for (int t = tid; t < 2048; t += 1024) s[t] = (t < n) ? g_cand[b][t] : 0ULL;
    __syncthreads();
    for (int k = 2; k <= 2048; k <<= 1) {
        for (int j = k >> 1; j > 0; j >>= 1) {
            int i = ((tid & ~(j - 1)) << 1) | (tid & (j - 1));
            int p = i | j;
            bool desc = ((i & k) == 0);
            unsigned long long a = s[i], c = s[p];
            if (desc ? (a < c) : (a > c)) { s[i] = c; s[p] = a; }
            __syncthreads();
        }
    }
    if (tid < TOPK) {
        unsigned long long v = s[tid];
        if (v != 0ULL) {
            unsigned idx = ~(unsigned)(v & 0xFFFFFFFFull);
            g_ts[b][tid] = g_scores[(size_t)b * NA + idx];
            g_tb[b][tid] = g_boxes[(size_t)b * NA + idx];
        } else {
            g_ts[b][tid] = -1e9f;
            g_tb[b][tid] = make_float4(0.f, 0.f, 0.f, 0.f);
        }
    }
}

// ---------------- greedy NMS + compaction to (300,5) ----------------
__global__ void nms_out_kernel(float* __restrict__ out) {
    int b = blockIdx.x, j = threadIdx.x;
    __shared__ float sx1[TOPK], sy1[TOPK], sx2[TOPK], sy2[TOPK], sar[TOPK];
    __shared__ int   supp[TOPK];
    __shared__ int   scn[1024];

    float bx1 = 0.f, by1 = 0.f, bx2 = 0.f, by2 = 0.f, barea = 0.f, bscore = -1e9f;
    if (j < TOPK) {
        float4 bb = g_tb[b][j];
        bx1 = bb.x; by1 = bb.y; bx2 = bb.z; by2 = bb.w;
        barea = __fmul_rn(__fsub_rn(bx2, bx1), __fsub_rn(by2, by1));
        bscore = g_ts[b][j];
        sx1[j] = bx1; sy1[j] = by1; sx2[j] = bx2; sy2[j] = by2; sar[j] = barea;
        supp[j] = 0;
    }
    __syncthreads();

    for (int i = 0; i < TOPK; i++) {
        if (!supp[i]) {
            if (j > i && j < TOPK && !supp[j]) {
                float xx1 = fmaxf(sx1[i], bx1);
                float yy1 = fmaxf(sy1[i], by1);
                float xx2 = fminf(sx2[i], bx2);
                float yy2 = fminf(sy2[i], by2);
                float inter = __fmul_rn(fmaxf(__fsub_rn(xx2, xx1), 0.f),
                                        fmaxf(__fsub_rn(yy2, yy1), 0.f));
                float den = __fadd_rn(__fsub_rn(__fadd_rn(sar[i], barea), inter), 1e-9f);
                float iou = __fdiv_rn(inter, den);
                if (iou > 0.7f) supp[j] = 1;
            }
            __syncthreads();
        }
    }

    int keepf = (j < TOPK && !supp[j] && bscore > -1e8f) ? 1 : 0;

    for (int t = j; t < POST * 5; t += 1024) out[(size_t)b * POST * 5 + t] = 0.f;

    scn[j] = keepf;
    __syncthreads();
    for (int off = 1; off < 1024; off <<= 1) {
        int v = (j >= off) ? scn[j - off] : 0;
        __syncthreads();
        scn[j] += v;
        __syncthreads();
    }
    int rank = scn[j] - keepf;
    if (keepf && rank < POST) {
        float* o = out + (size_t)b * POST * 5 + (size_t)rank * 5;
        o[0] = bx1; o[1] = by1; o[2] = bx2; o[3] = by2; o[4] = bscore;
    }
}

// ---------------- host launcher ----------------
extern "C" void kernel_launch(void* const* d_in, const int* in_sizes, int n_in,
                              void* d_out, int out_size) {
    const float* p[5] = {0, 0, 0, 0, 0};
    const float *convw = 0, *convb = 0, *clsw = 0, *clsb = 0, *boxw = 0, *boxb = 0;
    for (int i = 0; i < n_in; i++) {
        switch (in_sizes[i]) {
            case 33554432: p[0]  = (const float*)d_in[i]; break; // p2 (2,256,256,256)
            case 8388608:  p[1]  = (const float*)d_in[i]; break; // p3
            case 2097152:  p[2]  = (const float*)d_in[i]; break; // p4
            case 524288:   p[3]  = (const float*)d_in[i]; break; // p5
            case 131072:   p[4]  = (const float*)d_in[i]; break; // p6
            case 589824:   convw = (const float*)d_in[i]; break; // (256,256,3,3)
            case 256:      convb = (const float*)d_in[i]; break;
            case 768:      clsw  = (const float*)d_in[i]; break; // (3,256)
            case 3:        clsb  = (const float*)d_in[i]; break;
            case 3072:     boxw  = (const float*)d_in[i]; break; // (12,256)
            case 12:       boxb  = (const float*)d_in[i]; break;
        }
    }

    const int    Hs[5]      = {256, 128, 64, 32, 16};
    const int    strides[5] = {4, 8, 16, 32, 64};
    const float  sizes[5]   = {32.f, 64.f, 128.f, 256.f, 512.f};
    const int    offs[5]    = {0, 196608, 245760, 258048, 261120};
    const size_t xoffs[5]   = {0, 33554432, 41943040, 44040192, 44564480};

    // allow 73 KB dynamic smem for the conv (idempotent; not an allocation)
    static bool attr_set = false;
    if (!attr_set) {
        cudaFuncSetAttribute(conv3x3_relu_kernel,
                             cudaFuncAttributeMaxDynamicSharedMemorySize, CONV_SMEM);
        attr_set = true;
    }

    float* xbase;
    cudaGetSymbolAddress((void**)&xbase, g_x);

    auto conv = [&](int l) {
        int H = Hs[l], W = Hs[l];
        dim3 grid((W + 63) / 64, H / 2, 8);
        conv3x3_relu_kernel<<<grid, 256, CONV_SMEM>>>(p[l], convw, convb,
                                                      xbase + xoffs[l], H, W);
    };
    auto head = [&](int l) {
        int H = Hs[l], W = Hs[l];
        int HW = H * W;
        dim3 g2((HW + 255) / 256, 2);
        head_decode_kernel<<<g2, 256>>>(clsw, clsb, boxw, boxb,
                                        xbase + xoffs[l], H, W,
                                        strides[l], sizes[l], offs[l]);
    };

    // Launch order chosen so the ncu capture window (observed to land around
    // launch index 3-5) hits the big conv kernels: idx3 = conv(p2), idx5 = conv(p3).
    conv(4);      // 0: conv p6
    conv(3);      // 1: conv p5
    conv(2);      // 2: conv p4
    conv(0);      // 3: conv p2   <-- profile target
    head(4);      // 4: head p6
    conv(1);      // 5: conv p3   <-- profile target (hedge)
    head(3);      // 6: head p5
    head(2);      // 7: head p4
    head(0);      // 8: head p2
    head(1);      // 9: head p3

    zero_hist_kernel<<<512, 256>>>();
    hist_hi_kernel<<<1024, 256>>>();
    scan_hi_kernel<<<2, 1024>>>();
    zero_hist_kernel<<<512, 256>>>();
    hist_lo_kernel<<<1024, 256>>>();
    scan_lo_kernel<<<2, 1024>>>();
    compact_kernel<<<1024, 256>>>();
    sort_topk_kernel<<<2, 1024>>>();
    nms_out_kernel<<<2, 1024>>>((float*)d_out);
}

// round 8
// speedup vs baseline: 1.1618x; 1.1618x over previous
#include <cuda_runtime.h>
#include <cstdint>

#define NA 261888
#define TOPK 1000
#define POST 300

// ---------------- static scratch (no allocations allowed) ----------------
__device__ float              g_x[(size_t)44695552]; // per-level conv outputs
__device__ float              g_wt[589824];          // transformed conv weights
__device__ float              g_scores[2 * NA];
__device__ float4             g_boxes[2 * NA];
__device__ unsigned           g_hist[2][65536];
__device__ unsigned           g_selHi[2];
__device__ unsigned           g_above[2];
__device__ unsigned           g_T[2];
__device__ int                g_candCnt[2];
__device__ unsigned long long g_cand[2][2048];
__device__ float              g_ts[2][1024];
__device__ float4             g_tb[2][1024];

// ---------------- f32x2 packed-FMA helpers (Blackwell) ----------------
__device__ __forceinline__ unsigned long long pack_dup(float v) {
    unsigned long long r;
    unsigned u = __float_as_uint(v);
    asm("mov.b64 %0, {%1, %1};" : "=l"(r) : "r"(u));
    return r;
}
__device__ __forceinline__ void fma2(unsigned long long& acc,
                                     unsigned long long a,
                                     unsigned long long b) {
    asm("fma.rn.f32x2 %0, %1, %2, %0;" : "+l"(acc) : "l"(a), "l"(b));
}
__device__ __forceinline__ void unpack2(unsigned long long v, float& lo, float& hi) {
    unsigned a, b;
    asm("mov.b64 {%0, %1}, %2;" : "=r"(a), "=r"(b) : "l"(v));
    lo = __uint_as_float(a);
    hi = __uint_as_float(b);
}

// ---------------- XLA-exact sigmoid: 0.5 + 0.5*fast_tanh(0.5*x) ----------------
__device__ __forceinline__ float xla_fast_tanh(float x) {
    const float kBound = 7.90531110763549805f;
    float xc = fminf(fmaxf(x, -kBound), kBound);
    float x2 = __fmul_rn(xc, xc);
    float n = __fadd_rn(__fmul_rn(x2, -2.76076847742355e-16f), 2.00018790482477e-13f);
    n = __fadd_rn(__fmul_rn(x2, n), -8.60467152213735e-11f);
    n = __fadd_rn(__fmul_rn(x2, n),  5.12229709037114e-08f);
    n = __fadd_rn(__fmul_rn(x2, n),  1.48572235717979e-05f);
    n = __fadd_rn(__fmul_rn(x2, n),  6.37261928875436e-04f);
    n = __fadd_rn(__fmul_rn(x2, n),  4.89352455891786e-03f);
    n = __fmul_rn(xc, n);
    float d = __fadd_rn(__fmul_rn(x2, 1.19825839466702e-06f), 1.18534705686654e-04f);
    d = __fadd_rn(__fmul_rn(x2, d), 2.26843463243900e-03f);
    d = __fadd_rn(__fmul_rn(x2, d), 4.89352518554385e-03f);
    float t = __fdiv_rn(n, d);
    return (fabsf(x) < 0.0004f) ? x : t;
}
__device__ __forceinline__ float xla_sigmoid(float l) {
    float t = xla_fast_tanh(__fmul_rn(0.5f, l));
    return __fadd_rn(0.5f, __fmul_rn(0.5f, t));
}

// ---------------- weight transform: w[oc][ic][3][3] -> wt[g][ic][k][ocl] ----------------
// g = oc/64, ocl = oc%64. Value-preserving relayout only.
__global__ void wtrans_kernel(const float* __restrict__ w, float* __restrict__ wt) {
    int i = blockIdx.x * 256 + threadIdx.x;
    if (i >= 589824) return;
    int g   = i / 147456;
    int rem = i % 147456;
    int ic  = rem / 576;
    int r2  = rem % 576;
    int k   = r2 / 64;
    int ocl = r2 % 64;
    wt[i] = w[((size_t)(g * 64 + ocl) * 256 + ic) * 9 + k];
}

// ---------------- conv 3x3 (256->256) + bias + relu ----------------
// Tile 2 rows x 64 cols x 64 oc, 256 threads. Per-output FMA chain order
// (ic asc, ky asc, kx asc) identical to rounds 4-7 -> bitwise-identical output.
// Staging is division-free: warp ty stages input channel ic=ty; weights are a
// flat contiguous float4 copy from the pre-transformed tensor.
__global__ void __launch_bounds__(256, 2)
conv3x3_relu_kernel(const float* __restrict__ in,
                    const float* __restrict__ wt,
                    const float* __restrict__ bias,
                    float* __restrict__ xout,
                    int H, int W) {
    __shared__ unsigned long long s_in2[8][4][66];  // duplicated {v,v}
    __shared__ float              s_w[8][9][64];    // [ic][k][oc] (contiguous copy)

    const int tx  = threadIdx.x & 31;
    const int ty  = threadIdx.x >> 5;
    const int x0  = blockIdx.x * 64;
    const int y0  = blockIdx.y * 2;
    const int b   = blockIdx.z >> 2;
    const int g   = blockIdx.z & 3;
    const int ocb = g * 64;

    unsigned long long acc2[4][4];
#pragma unroll
    for (int i = 0; i < 4; i++)
#pragma unroll
        for (int j = 0; j < 4; j++) acc2[i][j] = 0ULL;

    const float* inB = in + (size_t)b * 256 * H * W;
    const float* wtg = wt + (size_t)g * 147456;

    for (int icb = 0; icb < 256; icb += 8) {
        // ---- input staging: warp ty handles ic = ty (no div/mod) ----
        {
            const float* src = inB + (size_t)(icb + ty) * H * W;
#pragma unroll
            for (int r = 0; r < 4; r++) {
                int yy = y0 + r - 1;
                bool yok = (yy >= 0 && yy < H);
                const float* row = src + (size_t)yy * W;
                int xxA = x0 + tx - 1;
                int xxB = x0 + tx + 31;
                float vA = (yok && xxA >= 0 && xxA < W) ? row[xxA] : 0.f;
                float vB = (yok && xxB < W) ? row[xxB] : 0.f;
                s_in2[ty][r][tx]      = pack_dup(vA);
                s_in2[ty][r][tx + 32] = pack_dup(vB);
                if (tx < 2) {
                    int xxC = x0 + tx + 63;
                    float vC = (yok && xxC < W) ? row[xxC] : 0.f;
                    s_in2[ty][r][tx + 64] = pack_dup(vC);
                }
            }
        }
        // ---- weight staging: flat contiguous float4 copy ----
        {
            const float4* src4 = reinterpret_cast<const float4*>(wtg + (size_t)icb * 576);
            float4* dst4 = reinterpret_cast<float4*>(&s_w[0][0][0]);
            for (int e = threadIdx.x; e < 1152; e += 256) dst4[e] = src4[e];
        }
        __syncthreads();

#pragma unroll
        for (int ic = 0; ic < 8; ic++) {
            unsigned long long pa[4][3], pb[4][3];
#pragma unroll
            for (int r = 0; r < 4; r++)
#pragma unroll
                for (int c = 0; c < 3; c++) {
                    pa[r][c] = s_in2[ic][r][tx + c];
                    pb[r][c] = s_in2[ic][r][tx + 32 + c];
                }
#pragma unroll
            for (int k = 0; k < 9; k++) {
                const int ky = k / 3, kx = k % 3;
                ulonglong2 wv0 = *reinterpret_cast<const ulonglong2*>(&s_w[ic][k][8 * ty]);
                ulonglong2 wv1 = *reinterpret_cast<const ulonglong2*>(&s_w[ic][k][8 * ty + 4]);
                fma2(acc2[0][0], pa[ky][kx],     wv0.x);
                fma2(acc2[0][1], pb[ky][kx],     wv0.x);
                fma2(acc2[0][2], pa[ky + 1][kx], wv0.x);
                fma2(acc2[0][3], pb[ky + 1][kx], wv0.x);
                fma2(acc2[1][0], pa[ky][kx],     wv0.y);
                fma2(acc2[1][1], pb[ky][kx],     wv0.y);
                fma2(acc2[1][2], pa[ky + 1][kx], wv0.y);
                fma2(acc2[1][3], pb[ky + 1][kx], wv0.y);
                fma2(acc2[2][0], pa[ky][kx],     wv1.x);
                fma2(acc2[2][1], pb[ky][kx],     wv1.x);
                fma2(acc2[2][2], pa[ky + 1][kx], wv1.x);
                fma2(acc2[2][3], pb[ky + 1][kx], wv1.x);
                fma2(acc2[3][0], pa[ky][kx],     wv1.y);
                fma2(acc2[3][1], pb[ky][kx],     wv1.y);
                fma2(acc2[3][2], pa[ky + 1][kx], wv1.y);
                fma2(acc2[3][3], pb[ky + 1][kx], wv1.y);
            }
        }
        __syncthreads();
    }

#pragma unroll
    for (int op = 0; op < 4; op++) {
        const int ocl = ocb + 8 * ty + 2 * op;
        const float bv0 = bias[ocl];
        const float bv1 = bias[ocl + 1];
        float* out0 = xout + (size_t)(b * 256 + ocl) * H * W;
        float* out1 = out0 + (size_t)H * W;
#pragma unroll
        for (int q = 0; q < 4; q++) {
            float v0, v1;
            unpack2(acc2[op][q], v0, v1);
            int y = y0 + (q >> 1);
            int x = (q & 1) ? (x0 + 32 + tx) : (x0 + tx);
            if (x < W) {
                out0[(size_t)y * W + x] = fmaxf(__fadd_rn(v0, bv0), 0.f);
                out1[(size_t)y * W + x] = fmaxf(__fadd_rn(v1, bv1), 0.f);
            }
        }
    }
}

// ---------------- 1x1 heads + anchor decode + sigmoid + mask ----------------
__global__ void head_decode_kernel(const float* __restrict__ clsw, const float* __restrict__ clsb,
                                   const float* __restrict__ boxw, const float* __restrict__ boxb,
                                   const float* __restrict__ xin,
                                   int H, int W, int stride, float asize, int lvl_off) {
    __shared__ float s_cw[3 * 256];
    __shared__ float s_bw[12 * 256];
    for (int e = threadIdx.x; e < 3 * 256; e += blockDim.x) s_cw[e] = clsw[e];
    for (int e = threadIdx.x; e < 12 * 256; e += blockDim.x) s_bw[e] = boxw[e];
    __syncthreads();

    int pix = blockIdx.x * blockDim.x + threadIdx.x;
    int b   = blockIdx.y;
    int HW  = H * W;
    if (pix >= HW) return;

    const float* xp = xin + (size_t)b * 256 * HW + pix;
    float o[3]  = {0.f, 0.f, 0.f};
    float d[12];
#pragma unroll
    for (int j = 0; j < 12; j++) d[j] = 0.f;

    for (int c = 0; c < 256; c++) {
        float v = xp[(size_t)c * HW];
        o[0] += v * s_cw[c];
        o[1] += v * s_cw[256 + c];
        o[2] += v * s_cw[512 + c];
#pragma unroll
        for (int j = 0; j < 12; j++) d[j] += v * s_bw[j * 256 + c];
    }
#pragma unroll
    for (int a = 0; a < 3; a++) o[a] = __fadd_rn(o[a], clsb[a]);
#pragma unroll
    for (int j = 0; j < 12; j++) d[j] = __fadd_rn(d[j], boxb[j]);

    int yy = pix / W, xx = pix % W;
    float xs = (float)(xx * stride), ys = (float)(yy * stride);
    const float ratios[3] = {0.5f, 1.0f, 2.0f};
#pragma unroll
    for (int a = 0; a < 3; a++) {
        float s  = sqrtf(ratios[a]);
        float hh = __fmul_rn(asize, s);
        float ww = __fdiv_rn(asize, s);
        float ax1 = __fadd_rn(xs, -0.5f * ww);
        float ax2 = __fadd_rn(xs,  0.5f * ww);
        float ay1 = __fadd_rn(ys, -0.5f * hh);
        float ay2 = __fadd_rn(ys,  0.5f * hh);
        float aw = __fsub_rn(ax2, ax1);
        float ah = __fsub_rn(ay2, ay1);
        float ax = __fadd_rn(ax1, 0.5f * aw);
        float ay = __fadd_rn(ay1, 0.5f * ah);
        float dx = d[4 * a], dy = d[4 * a + 1], dw = d[4 * a + 2], dh = d[4 * a + 3];
        float cx = __fadd_rn(__fmul_rn(dx, aw), ax);
        float cy = __fadd_rn(__fmul_rn(dy, ah), ay);
        float pw = __fmul_rn(expf(dw), aw);
        float ph = __fmul_rn(expf(dh), ah);
        float x1 = __fsub_rn(cx, 0.5f * pw);
        float y1 = __fsub_rn(cy, 0.5f * ph);
        float x2 = __fadd_rn(cx, 0.5f * pw);
        float y2 = __fadd_rn(cy, 0.5f * ph);
        x1 = fminf(fmaxf(x1, 0.f), 1024.f);
        y1 = fminf(fmaxf(y1, 0.f), 1024.f);
        x2 = fminf(fmaxf(x2, 0.f), 1024.f);
        y2 = fminf(fmaxf(y2, 0.f), 1024.f);
        float ws = __fsub_rn(x2, x1), hs = __fsub_rn(y2, y1);
        bool valid = (ws >= 1.0f) && (hs >= 1.0f);
        float sc = xla_sigmoid(o[a]);
        float masked = valid ? sc : -1e9f;
        int aidx = lvl_off + pix * 3 + a;
        g_scores[(size_t)b * NA + aidx] = masked;
        g_boxes[(size_t)b * NA + aidx] = make_float4(x1, y1, x2, y2);
    }
}

// ---------------- top-k via 2-pass 16-bit radix select ----------------
__device__ __forceinline__ unsigned f2u(float f) {
    unsigned u = __float_as_uint(f);
    return (u & 0x80000000u) ? ~u : (u | 0x80000000u);
}

__global__ void zero_hist_kernel() {
    int i = blockIdx.x * blockDim.x + threadIdx.x;
    if (i < 2 * 65536) (&g_hist[0][0])[i] = 0u;
}

__global__ void hist_hi_kernel() {
    for (int i = blockIdx.x * blockDim.x + threadIdx.x; i < 2 * NA; i += gridDim.x * blockDim.x) {
        int b = i / NA;
        unsigned k = f2u(g_scores[i]);
        atomicAdd(&g_hist[b][k >> 16], 1u);
    }
}

__global__ void scan_hi_kernel() {
    int b = blockIdx.x, tid = threadIdx.x;
    __shared__ unsigned ssum[1024];
    unsigned tsum = 0;
    int base = tid * 64;
    for (int i = 0; i < 64; i++) tsum += g_hist[b][base + i];
    ssum[tid] = tsum;
    __syncthreads();
    for (int off = 1; off < 1024; off <<= 1) {
        unsigned v = (tid + off < 1024) ? ssum[tid + off] : 0u;
        __syncthreads();
        ssum[tid] += v;
        __syncthreads();
    }
    unsigned above = ssum[tid] - tsum;
    if (above < TOPK && above + tsum >= TOPK) {
        unsigned acc = above;
        for (int i = 63; i >= 0; i--) {
            unsigned c = g_hist[b][base + i];
            if (acc + c >= TOPK) { g_selHi[b] = (unsigned)(base + i); g_above[b] = acc; break; }
            acc += c;
        }
    }
}

__global__ void hist_lo_kernel() {
    for (int i = blockIdx.x * blockDim.x + threadIdx.x; i < 2 * NA; i += gridDim.x * blockDim.x) {
        int b = i / NA;
        unsigned k = f2u(g_scores[i]);
        if ((k >> 16) == g_selHi[b]) atomicAdd(&g_hist[b][k & 0xFFFFu], 1u);
    }
}

__global__ void scan_lo_kernel() {
    int b = blockIdx.x, tid = threadIdx.x;
    unsigned Kp = TOPK - g_above[b];
    __shared__ unsigned ssum[1024];
    unsigned tsum = 0;
    int base = tid * 64;
    for (int i = 0; i < 64; i++) tsum += g_hist[b][base + i];
    ssum[tid] = tsum;
    __syncthreads();
    for (int off = 1; off < 1024; off <<= 1) {
        unsigned v = (tid + off < 1024) ? ssum[tid + off] : 0u;
        __syncthreads();
        ssum[tid] += v;
        __syncthreads();
    }
    unsigned above = ssum[tid] - tsum;
    if (above < Kp && above + tsum >= Kp) {
        unsigned acc = above;
        for (int i = 63; i >= 0; i--) {
            unsigned c = g_hist[b][base + i];
            if (acc + c >= Kp) {
                g_T[b] = (g_selHi[b] << 16) | (unsigned)(base + i);
                break;
            }
            acc += c;
        }
    }
    if (tid == 0) g_candCnt[b] = 0;
}

__global__ void compact_kernel() {
    for (int i = blockIdx.x * blockDim.x + threadIdx.x; i < 2 * NA; i += gridDim.x * blockDim.x) {
        int b = i / NA;
        unsigned k = f2u(g_scores[i]);
        if (k >= g_T[b]) {
            int p = atomicAdd(&g_candCnt[b], 1);
            if (p < 2048) {
                unsigned idx = (unsigned)(i - b * NA);
                g_cand[b][p] = ((unsigned long long)k << 32) | (unsigned long long)(~idx);
            }
        }
    }
}

// Bitonic sort of <=2048 candidates, composite key (score desc, index asc)
__global__ void sort_topk_kernel() {
    int b = blockIdx.x, tid = threadIdx.x;
    __shared__ unsigned long long s[2048];
    int n = g_candCnt[b];
    if (n > 2048) n = 2048;
    for (int t = tid; t < 2048; t += 1024) s[t] = (t < n) ? g_cand[b][t] : 0ULL;
    __syncthreads();
    for (int k = 2; k <= 2048; k <<= 1) {
        for (int j = k >> 1; j > 0; j >>= 1) {
            int i = ((tid & ~(j - 1)) << 1) | (tid & (j - 1));
            int p = i | j;
            bool desc = ((i & k) == 0);
            unsigned long long a = s[i], c = s[p];
            if (desc ? (a < c) : (a > c)) { s[i] = c; s[p] = a; }
            __syncthreads();
        }
    }
    if (tid < TOPK) {
        unsigned long long v = s[tid];
        if (v != 0ULL) {
            unsigned idx = ~(unsigned)(v & 0xFFFFFFFFull);
            g_ts[b][tid] = g_scores[(size_t)b * NA + idx];
            g_tb[b][tid] = g_boxes[(size_t)b * NA + idx];
        } else {
            g_ts[b][tid] = -1e9f;
            g_tb[b][tid] = make_float4(0.f, 0.f, 0.f, 0.f);
        }
    }
}

// ---------------- greedy NMS + compaction to (300,5) ----------------
__global__ void nms_out_kernel(float* __restrict__ out) {
    int b = blockIdx.x, j = threadIdx.x;
    __shared__ float sx1[TOPK], sy1[TOPK], sx2[TOPK], sy2[TOPK], sar[TOPK];
    __shared__ int   supp[TOPK];
    __shared__ int   scn[1024];

    float bx1 = 0.f, by1 = 0.f, bx2 = 0.f, by2 = 0.f, barea = 0.f, bscore = -1e9f;
    if (j < TOPK) {
        float4 bb = g_tb[b][j];
        bx1 = bb.x; by1 = bb.y; bx2 = bb.z; by2 = bb.w;
        barea = __fmul_rn(__fsub_rn(bx2, bx1), __fsub_rn(by2, by1));
        bscore = g_ts[b][j];
        sx1[j] = bx1; sy1[j] = by1; sx2[j] = bx2; sy2[j] = by2; sar[j] = barea;
        supp[j] = 0;
    }
    __syncthreads();

    for (int i = 0; i < TOPK; i++) {
        if (!supp[i]) {
            if (j > i && j < TOPK && !supp[j]) {
                float xx1 = fmaxf(sx1[i], bx1);
                float yy1 = fmaxf(sy1[i], by1);
                float xx2 = fminf(sx2[i], bx2);
                float yy2 = fminf(sy2[i], by2);
                float inter = __fmul_rn(fmaxf(__fsub_rn(xx2, xx1), 0.f),
                                        fmaxf(__fsub_rn(yy2, yy1), 0.f));
                float den = __fadd_rn(__fsub_rn(__fadd_rn(sar[i], barea), inter), 1e-9f);
                float iou = __fdiv_rn(inter, den);
                if (iou > 0.7f) supp[j] = 1;
            }
            __syncthreads();
        }
    }

    int keepf = (j < TOPK && !supp[j] && bscore > -1e8f) ? 1 : 0;

    for (int t = j; t < POST * 5; t += 1024) out[(size_t)b * POST * 5 + t] = 0.f;

    scn[j] = keepf;
    __syncthreads();
    for (int off = 1; off < 1024; off <<= 1) {
        int v = (j >= off) ? scn[j - off] : 0;
        __syncthreads();
        scn[j] += v;
        __syncthreads();
    }
    int rank = scn[j] - keepf;
    if (keepf && rank < POST) {
        float* o = out + (size_t)b * POST * 5 + (size_t)rank * 5;
        o[0] = bx1; o[1] = by1; o[2] = bx2; o[3] = by2; o[4] = bscore;
    }
}

// ---------------- host launcher ----------------
extern "C" void kernel_launch(void* const* d_in, const int* in_sizes, int n_in,
                              void* d_out, int out_size) {
    const float* p[5] = {0, 0, 0, 0, 0};
    const float *convw = 0, *convb = 0, *clsw = 0, *clsb = 0, *boxw = 0, *boxb = 0;
    for (int i = 0; i < n_in; i++) {
        switch (in_sizes[i]) {
            case 33554432: p[0]  = (const float*)d_in[i]; break; // p2 (2,256,256,256)
            case 8388608:  p[1]  = (const float*)d_in[i]; break; // p3
            case 2097152:  p[2]  = (const float*)d_in[i]; break; // p4
            case 524288:   p[3]  = (const float*)d_in[i]; break; // p5
            case 131072:   p[4]  = (const float*)d_in[i]; break; // p6
            case 589824:   convw = (const float*)d_in[i]; break; // (256,256,3,3)
            case 256:      convb = (const float*)d_in[i]; break;
            case 768:      clsw  = (const float*)d_in[i]; break; // (3,256)
            case 3:        clsb  = (const float*)d_in[i]; break;
            case 3072:     boxw  = (const float*)d_in[i]; break; // (12,256)
            case 12:       boxb  = (const float*)d_in[i]; break;
        }
    }

    const int    Hs[5]      = {256, 128, 64, 32, 16};
    const int    strides[5] = {4, 8, 16, 32, 64};
    const float  sizes[5]   = {32.f, 64.f, 128.f, 256.f, 512.f};
    const int    offs[5]    = {0, 196608, 245760, 258048, 261120};
    const size_t xoffs[5]   = {0, 33554432, 41943040, 44040192, 44564480};

    float* xbase;
    cudaGetSymbolAddress((void**)&xbase, g_x);
    float* wtbase;
    cudaGetSymbolAddress((void**)&wtbase, g_wt);

    auto conv = [&](int l) {
        int H = Hs[l], W = Hs[l];
        dim3 grid((W + 63) / 64, H / 2, 8);
        conv3x3_relu_kernel<<<grid, 256>>>(p[l], wtbase, convb,
                                           xbase + xoffs[l], H, W);
    };
    auto head = [&](int l) {
        int H = Hs[l], W = Hs[l];
        int HW = H * W;
        dim3 g2((HW + 255) / 256, 2);
        head_decode_kernel<<<g2, 256>>>(clsw, clsb, boxw, boxb,
                                        xbase + xoffs[l], H, W,
                                        strides[l], sizes[l], offs[l]);
    };

    wtrans_kernel<<<(589824 + 255) / 256, 256>>>(convw, wtbase);   // 0

    // keep big convs in the ncu capture window (observed to land ~idx 3-5)
    conv(4);      // 1: conv p6
    conv(3);      // 2: conv p5
    conv(2);      // 3: conv p4
    conv(0);      // 4: conv p2   <-- profile target
    conv(1);      // 5: conv p3   <-- profile target (hedge)
    head(4);      // 6
    head(3);      // 7
    head(2);      // 8
    head(0);      // 9
    head(1);      // 10

    zero_hist_kernel<<<512, 256>>>();
    hist_hi_kernel<<<1024, 256>>>();
    scan_hi_kernel<<<2, 1024>>>();
    zero_hist_kernel<<<512, 256>>>();
    hist_lo_kernel<<<1024, 256>>>();
    scan_lo_kernel<<<2, 1024>>>();
    compact_kernel<<<1024, 256>>>();
    sort_topk_kernel<<<2, 1024>>>();
    nms_out_kernel<<<2, 1024>>>((float*)d_out);
}

// round 9
// speedup vs baseline: 1.2455x; 1.0720x over previous
#include <cuda_runtime.h>
#include <cstdint>

#define NA 261888
#define TOPK 1000
#define POST 300

// ---------------- static scratch (no allocations allowed) ----------------
__device__ float              g_x[(size_t)44695552]; // per-level conv outputs
__device__ float              g_wt[589824];          // transformed conv weights
__device__ float              g_scores[2 * NA];
__device__ float4             g_boxes[2 * NA];
__device__ unsigned           g_hist[2][65536];
__device__ unsigned           g_selHi[2];
__device__ unsigned           g_above[2];
__device__ unsigned           g_T[2];
__device__ int                g_candCnt[2];
__device__ unsigned long long g_cand[2][2048];
__device__ float              g_ts[2][1024];
__device__ float4             g_tb[2][1024];

// ---------------- f32x2 packed-FMA helpers (Blackwell) ----------------
__device__ __forceinline__ unsigned long long pack_dup(float v) {
    unsigned long long r;
    unsigned u = __float_as_uint(v);
    asm("mov.b64 %0, {%1, %1};" : "=l"(r) : "r"(u));
    return r;
}
__device__ __forceinline__ void fma2(unsigned long long& acc,
                                     unsigned long long a,
                                     unsigned long long b) {
    asm("fma.rn.f32x2 %0, %1, %2, %0;" : "+l"(acc) : "l"(a), "l"(b));
}
__device__ __forceinline__ void unpack2(unsigned long long v, float& lo, float& hi) {
    unsigned a, b;
    asm("mov.b64 {%0, %1}, %2;" : "=r"(a), "=r"(b) : "l"(v));
    lo = __uint_as_float(a);
    hi = __uint_as_float(b);
}

// ---------------- XLA-exact sigmoid: 0.5 + 0.5*fast_tanh(0.5*x) ----------------
__device__ __forceinline__ float xla_fast_tanh(float x) {
    const float kBound = 7.90531110763549805f;
    float xc = fminf(fmaxf(x, -kBound), kBound);
    float x2 = __fmul_rn(xc, xc);
    float n = __fadd_rn(__fmul_rn(x2, -2.76076847742355e-16f), 2.00018790482477e-13f);
    n = __fadd_rn(__fmul_rn(x2, n), -8.60467152213735e-11f);
    n = __fadd_rn(__fmul_rn(x2, n),  5.12229709037114e-08f);
    n = __fadd_rn(__fmul_rn(x2, n),  1.48572235717979e-05f);
    n = __fadd_rn(__fmul_rn(x2, n),  6.37261928875436e-04f);
    n = __fadd_rn(__fmul_rn(x2, n),  4.89352455891786e-03f);
    n = __fmul_rn(xc, n);
    float d = __fadd_rn(__fmul_rn(x2, 1.19825839466702e-06f), 1.18534705686654e-04f);
    d = __fadd_rn(__fmul_rn(x2, d), 2.26843463243900e-03f);
    d = __fadd_rn(__fmul_rn(x2, d), 4.89352518554385e-03f);
    float t = __fdiv_rn(n, d);
    return (fabsf(x) < 0.0004f) ? x : t;
}
__device__ __forceinline__ float xla_sigmoid(float l) {
    float t = xla_fast_tanh(__fmul_rn(0.5f, l));
    return __fadd_rn(0.5f, __fmul_rn(0.5f, t));
}

// ---------------- weight transform: w[oc][ic][3][3] -> wt[g][ic][k][ocl] ----------------
// g = oc/128, ocl = oc%128. Value-preserving relayout only.
__global__ void wtrans_kernel(const float* __restrict__ w, float* __restrict__ wt) {
    int i = blockIdx.x * 256 + threadIdx.x;
    if (i >= 589824) return;
    int g   = i / 294912;
    int rem = i % 294912;
    int ic  = rem / 1152;
    int r2  = rem % 1152;
    int k   = r2 / 128;
    int ocl = r2 % 128;
    wt[i] = w[((size_t)(g * 128 + ocl) * 256 + ic) * 9 + k];
}

// ---------------- conv 3x3 (256->256) + bias + relu ----------------
// Tile 2 rows x 64 cols x 128 oc, 256 threads. Thread (tx,ty): pixels
// (y0+{0,1}, x0+{tx,tx+32}), oc = g*128 + 16*ty + 2*op (op=0..7).
// Per-output FMA chain order (ic asc, ky asc, kx asc) identical to rounds
// 4-8 -> bitwise-identical output. Sliding 2-row activation window keeps
// register pressure under the 2-CTA/SM cap.
#define CONV_SMEM (36864 + 16896)   // s_w[8][9][128] f32 + s_in2[8][4][66] u64

// one k-tap: 8 oc-pairs x 4 px = 32 FFMA2; wk points at s_w[ic][k][16*ty]
__device__ __forceinline__ void conv_k_step(unsigned long long (&acc2)[8][4],
                                            const float* wk,
                                            unsigned long long a0, unsigned long long b0,
                                            unsigned long long a1, unsigned long long b1) {
#pragma unroll
    for (int m = 0; m < 4; m++) {
        ulonglong2 wv = *reinterpret_cast<const ulonglong2*>(wk + 4 * m);
        fma2(acc2[2 * m][0],     a0, wv.x);
        fma2(acc2[2 * m][1],     b0, wv.x);
        fma2(acc2[2 * m][2],     a1, wv.x);
        fma2(acc2[2 * m][3],     b1, wv.x);
        fma2(acc2[2 * m + 1][0], a0, wv.y);
        fma2(acc2[2 * m + 1][1], b0, wv.y);
        fma2(acc2[2 * m + 1][2], a1, wv.y);
        fma2(acc2[2 * m + 1][3], b1, wv.y);
    }
}

__global__ void __launch_bounds__(256, 2)
conv3x3_relu_kernel(const float* __restrict__ in,
                    const float* __restrict__ wt,
                    const float* __restrict__ bias,
                    float* __restrict__ xout,
                    int H, int W) {
    extern __shared__ char smemraw[];
    float* s_w = reinterpret_cast<float*>(smemraw);                                  // [8][9][128]
    unsigned long long* s_in2 = reinterpret_cast<unsigned long long*>(smemraw + 36864); // [8][4][66]

    const int tx = threadIdx.x & 31;
    const int ty = threadIdx.x >> 5;
    const int x0 = blockIdx.x * 64;
    const int y0 = blockIdx.y * 2;
    const int b  = blockIdx.z >> 1;
    const int g  = blockIdx.z & 1;

    unsigned long long acc2[8][4];
#pragma unroll
    for (int i = 0; i < 8; i++)
#pragma unroll
        for (int j = 0; j < 4; j++) acc2[i][j] = 0ULL;

    const float* inB = in + (size_t)b * 256 * H * W;
    const float* wtg = wt + (size_t)g * 294912;

    for (int icb = 0; icb < 256; icb += 8) {
        // ---- input staging: warp ty stages ic = ty (division-free) ----
        {
            const float* src = inB + (size_t)(icb + ty) * H * W;
#pragma unroll
            for (int r = 0; r < 4; r++) {
                int yy = y0 + r - 1;
                bool yok = (yy >= 0 && yy < H);
                const float* row = src + (size_t)yy * W;
                int xxA = x0 + tx - 1;
                int xxB = x0 + tx + 31;
                float vA = (yok && xxA >= 0 && xxA < W) ? row[xxA] : 0.f;
                float vB = (yok && xxB < W) ? row[xxB] : 0.f;
                s_in2[ty * 264 + r * 66 + tx]      = pack_dup(vA);
                s_in2[ty * 264 + r * 66 + tx + 32] = pack_dup(vB);
                if (tx < 2) {
                    int xxC = x0 + tx + 63;
                    float vC = (yok && xxC < W) ? row[xxC] : 0.f;
                    s_in2[ty * 264 + r * 66 + tx + 64] = pack_dup(vC);
                }
            }
        }
        // ---- weight staging: flat contiguous float4 copy ----
        {
            const float4* src4 = reinterpret_cast<const float4*>(wtg + (size_t)icb * 1152);
            float4* dst4 = reinterpret_cast<float4*>(s_w);
            for (int e = threadIdx.x; e < 2304; e += 256) dst4[e] = src4[e];
        }
        __syncthreads();

#pragma unroll
        for (int ic = 0; ic < 8; ic++) {
            const unsigned long long* bi = s_in2 + ic * 264;
            const float* wk = s_w + ic * 1152 + 16 * ty;

            unsigned long long A0[3], B0[3], A1[3], B1[3];
            unsigned long long A2[3], B2[3], A3[3], B3[3];
#pragma unroll
            for (int c = 0; c < 3; c++) {
                A0[c] = bi[c + tx];           B0[c] = bi[c + tx + 32];
                A1[c] = bi[66 + c + tx];      B1[c] = bi[66 + c + tx + 32];
            }
            // ky = 0 (k = 0,1,2): output rows use input rows 0,1
#pragma unroll
            for (int kx = 0; kx < 3; kx++)
                conv_k_step(acc2, wk + kx * 128, A0[kx], B0[kx], A1[kx], B1[kx]);
#pragma unroll
            for (int c = 0; c < 3; c++) {
                A2[c] = bi[132 + c + tx];     B2[c] = bi[132 + c + tx + 32];
            }
            // ky = 1 (k = 3,4,5): input rows 1,2
#pragma unroll
            for (int kx = 0; kx < 3; kx++)
                conv_k_step(acc2, wk + (3 + kx) * 128, A1[kx], B1[kx], A2[kx], B2[kx]);
#pragma unroll
            for (int c = 0; c < 3; c++) {
                A3[c] = bi[198 + c + tx];     B3[c] = bi[198 + c + tx + 32];
            }
            // ky = 2 (k = 6,7,8): input rows 2,3
#pragma unroll
            for (int kx = 0; kx < 3; kx++)
                conv_k_step(acc2, wk + (6 + kx) * 128, A2[kx], B2[kx], A3[kx], B3[kx]);
        }
        __syncthreads();
    }

#pragma unroll
    for (int op = 0; op < 8; op++) {
        const int ocl = g * 128 + 16 * ty + 2 * op;
        const float bv0 = bias[ocl];
        const float bv1 = bias[ocl + 1];
        float* out0 = xout + (size_t)(b * 256 + ocl) * H * W;
        float* out1 = out0 + (size_t)H * W;
#pragma unroll
        for (int q = 0; q < 4; q++) {
            float v0, v1;
            unpack2(acc2[op][q], v0, v1);
            int y = y0 + (q >> 1);
            int x = (q & 1) ? (x0 + 32 + tx) : (x0 + tx);
            if (x < W) {
                out0[(size_t)y * W + x] = fmaxf(__fadd_rn(v0, bv0), 0.f);
                out1[(size_t)y * W + x] = fmaxf(__fadd_rn(v1, bv1), 0.f);
            }
        }
    }
}

// ---------------- 1x1 heads + anchor decode + sigmoid + mask ----------------
__global__ void head_decode_kernel(const float* __restrict__ clsw, const float* __restrict__ clsb,
                                   const float* __restrict__ boxw, const float* __restrict__ boxb,
                                   const float* __restrict__ xin,
                                   int H, int W, int stride, float asize, int lvl_off) {
    __shared__ float s_cw[3 * 256];
    __shared__ float s_bw[12 * 256];
    for (int e = threadIdx.x; e < 3 * 256; e += blockDim.x) s_cw[e] = clsw[e];
    for (int e = threadIdx.x; e < 12 * 256; e += blockDim.x) s_bw[e] = boxw[e];
    __syncthreads();

    int pix = blockIdx.x * blockDim.x + threadIdx.x;
    int b   = blockIdx.y;
    int HW  = H * W;
    if (pix >= HW) return;

    const float* xp = xin + (size_t)b * 256 * HW + pix;
    float o[3]  = {0.f, 0.f, 0.f};
    float d[12];
#pragma unroll
    for (int j = 0; j < 12; j++) d[j] = 0.f;

    for (int c = 0; c < 256; c++) {
        float v = xp[(size_t)c * HW];
        o[0] += v * s_cw[c];
        o[1] += v * s_cw[256 + c];
        o[2] += v * s_cw[512 + c];
#pragma unroll
        for (int j = 0; j < 12; j++) d[j] += v * s_bw[j * 256 + c];
    }
#pragma unroll
    for (int a = 0; a < 3; a++) o[a] = __fadd_rn(o[a], clsb[a]);
#pragma unroll
    for (int j = 0; j < 12; j++) d[j] = __fadd_rn(d[j], boxb[j]);

    int yy = pix / W, xx = pix % W;
    float xs = (float)(xx * stride), ys = (float)(yy * stride);
    const float ratios[3] = {0.5f, 1.0f, 2.0f};
#pragma unroll
    for (int a = 0; a < 3; a++) {
        float s  = sqrtf(ratios[a]);
        float hh = __fmul_rn(asize, s);
        float ww = __fdiv_rn(asize, s);
        float ax1 = __fadd_rn(xs, -0.5f * ww);
        float ax2 = __fadd_rn(xs,  0.5f * ww);
        float ay1 = __fadd_rn(ys, -0.5f * hh);
        float ay2 = __fadd_rn(ys,  0.5f * hh);
        float aw = __fsub_rn(ax2, ax1);
        float ah = __fsub_rn(ay2, ay1);
        float ax = __fadd_rn(ax1, 0.5f * aw);
        float ay = __fadd_rn(ay1, 0.5f * ah);
        float dx = d[4 * a], dy = d[4 * a + 1], dw = d[4 * a + 2], dh = d[4 * a + 3];
        float cx = __fadd_rn(__fmul_rn(dx, aw), ax);
        float cy = __fadd_rn(__fmul_rn(dy, ah), ay);
        float pw = __fmul_rn(expf(dw), aw);
        float ph = __fmul_rn(expf(dh), ah);
        float x1 = __fsub_rn(cx, 0.5f * pw);
        float y1 = __fsub_rn(cy, 0.5f * ph);
        float x2 = __fadd_rn(cx, 0.5f * pw);
        float y2 = __fadd_rn(cy, 0.5f * ph);
        x1 = fminf(fmaxf(x1, 0.f), 1024.f);
        y1 = fminf(fmaxf(y1, 0.f), 1024.f);
        x2 = fminf(fmaxf(x2, 0.f), 1024.f);
        y2 = fminf(fmaxf(y2, 0.f), 1024.f);
        float ws = __fsub_rn(x2, x1), hs = __fsub_rn(y2, y1);
        bool valid = (ws >= 1.0f) && (hs >= 1.0f);
        float sc = xla_sigmoid(o[a]);
        float masked = valid ? sc : -1e9f;
        int aidx = lvl_off + pix * 3 + a;
        g_scores[(size_t)b * NA + aidx] = masked;
        g_boxes[(size_t)b * NA + aidx] = make_float4(x1, y1, x2, y2);
    }
}

// ---------------- top-k via 2-pass 16-bit radix select ----------------
__device__ __forceinline__ unsigned f2u(float f) {
    unsigned u = __float_as_uint(f);
    return (u & 0x80000000u) ? ~u : (u | 0x80000000u);
}

__global__ void zero_hist_kernel() {
    int i = blockIdx.x * blockDim.x + threadIdx.x;
    if (i < 2 * 65536) (&g_hist[0][0])[i] = 0u;
}

__global__ void hist_hi_kernel() {
    for (int i = blockIdx.x * blockDim.x + threadIdx.x; i < 2 * NA; i += gridDim.x * blockDim.x) {
        int b = i / NA;
        unsigned k = f2u(g_scores[i]);
        atomicAdd(&g_hist[b][k >> 16], 1u);
    }
}

__global__ void scan_hi_kernel() {
    int b = blockIdx.x, tid = threadIdx.x;
    __shared__ unsigned ssum[1024];
    unsigned tsum = 0;
    int base = tid * 64;
    for (int i = 0; i < 64; i++) tsum += g_hist[b][base + i];
    ssum[tid] = tsum;
    __syncthreads();
    for (int off = 1; off < 1024; off <<= 1) {
        unsigned v = (tid + off < 1024) ? ssum[tid + off] : 0u;
        __syncthreads();
        ssum[tid] += v;
        __syncthreads();
    }
    unsigned above = ssum[tid] - tsum;
    if (above < TOPK && above + tsum >= TOPK) {
        unsigned acc = above;
        for (int i = 63; i >= 0; i--) {
            unsigned c = g_hist[b][base + i];
            if (acc + c >= TOPK) { g_selHi[b] = (unsigned)(base + i); g_above[b] = acc; break; }
            acc += c;
        }
    }
}

__global__ void hist_lo_kernel() {
    for (int i = blockIdx.x * blockDim.x + threadIdx.x; i < 2 * NA; i += gridDim.x * blockDim.x) {
        int b = i / NA;
        unsigned k = f2u(g_scores[i]);
        if ((k >> 16) == g_selHi[b]) atomicAdd(&g_hist[b][k & 0xFFFFu], 1u);
    }
}

__global__ void scan_lo_kernel() {
    int b = blockIdx.x, tid = threadIdx.x;
    unsigned Kp = TOPK - g_above[b];
    __shared__ unsigned ssum[1024];
    unsigned tsum = 0;
    int base = tid * 64;
    for (int i = 0; i < 64; i++) tsum += g_hist[b][base + i];
    ssum[tid] = tsum;
    __syncthreads();
    for (int off = 1; off < 1024; off <<= 1) {
        unsigned v = (tid + off < 1024) ? ssum[tid + off] : 0u;
        __syncthreads();
        ssum[tid] += v;
        __syncthreads();
    }
    unsigned above = ssum[tid] - tsum;
    if (above < Kp && above + tsum >= Kp) {
        unsigned acc = above;
        for (int i = 63; i >= 0; i--) {
            unsigned c = g_hist[b][base + i];
            if (acc + c >= Kp) {
                g_T[b] = (g_selHi[b] << 16) | (unsigned)(base + i);
                break;
            }
            acc += c;
        }
    }
    if (tid == 0) g_candCnt[b] = 0;
}

__global__ void compact_kernel() {
    for (int i = blockIdx.x * blockDim.x + threadIdx.x; i < 2 * NA; i += gridDim.x * blockDim.x) {
        int b = i / NA;
        unsigned k = f2u(g_scores[i]);
        if (k >= g_T[b]) {
            int p = atomicAdd(&g_candCnt[b], 1);
            if (p < 2048) {
                unsigned idx = (unsigned)(i - b * NA);
                g_cand[b][p] = ((unsigned long long)k << 32) | (unsigned long long)(~idx);
            }
        }
    }
}

// Bitonic sort of <=2048 candidates, composite key (score desc, index asc)
__global__ void sort_topk_kernel() {
    int b = blockIdx.x, tid = threadIdx.x;
    __shared__ unsigned long long s[2048];
    int n = g_candCnt[b];
    if (n > 2048) n = 2048;
    for (int t = tid; t < 2048; t += 1024) s[t] = (t < n) ? g_cand[b][t] : 0ULL;
    __syncthreads();
    for (int k = 2; k <= 2048; k <<= 1) {
        for (int j = k >> 1; j > 0; j >>= 1) {
            int i = ((tid & ~(j - 1)) << 1) | (tid & (j - 1));
            int p = i | j;
            bool desc = ((i & k) == 0);
            unsigned long long a = s[i], c = s[p];
            if (desc ? (a < c) : (a > c)) { s[i] = c; s[p] = a; }
            __syncthreads();
        }
    }
    if (tid < TOPK) {
        unsigned long long v = s[tid];
        if (v != 0ULL) {
            unsigned idx = ~(unsigned)(v & 0xFFFFFFFFull);
            g_ts[b][tid] = g_scores[(size_t)b * NA + idx];
            g_tb[b][tid] = g_boxes[(size_t)b * NA + idx];
        } else {
            g_ts[b][tid] = -1e9f;
            g_tb[b][tid] = make_float4(0.f, 0.f, 0.f, 0.f);
        }
    }
}

// ---------------- greedy NMS + compaction to (300,5) ----------------
__global__ void nms_out_kernel(float* __restrict__ out) {
    int b = blockIdx.x, j = threadIdx.x;
    __shared__ float sx1[TOPK], sy1[TOPK], sx2[TOPK], sy2[TOPK], sar[TOPK];
    __shared__ int   supp[TOPK];
    __shared__ int   scn[1024];

    float bx1 = 0.f, by1 = 0.f, bx2 = 0.f, by2 = 0.f, barea = 0.f, bscore = -1e9f;
    if (j < TOPK) {
        float4 bb = g_tb[b][j];
        bx1 = bb.x; by1 = bb.y; bx2 = bb.z; by2 = bb.w;
        barea = __fmul_rn(__fsub_rn(bx2, bx1), __fsub_rn(by2, by1));
        bscore = g_ts[b][j];
        sx1[j] = bx1; sy1[j] = by1; sx2[j] = bx2; sy2[j] = by2; sar[j] = barea;
        supp[j] = 0;
    }
    __syncthreads();

    for (int i = 0; i < TOPK; i++) {
        if (!supp[i]) {
            if (j > i && j < TOPK && !supp[j]) {
                float xx1 = fmaxf(sx1[i], bx1);
                float yy1 = fmaxf(sy1[i], by1);
                float xx2 = fminf(sx2[i], bx2);
                float yy2 = fminf(sy2[i], by2);
                float inter = __fmul_rn(fmaxf(__fsub_rn(xx2, xx1), 0.f),
                                        fmaxf(__fsub_rn(yy2, yy1), 0.f));
                float den = __fadd_rn(__fsub_rn(__fadd_rn(sar[i], barea), inter), 1e-9f);
                float iou = __fdiv_rn(inter, den);
                if (iou > 0.7f) supp[j] = 1;
            }
            __syncthreads();
        }
    }

    int keepf = (j < TOPK && !supp[j] && bscore > -1e8f) ? 1 : 0;

    for (int t = j; t < POST * 5; t += 1024) out[(size_t)b * POST * 5 + t] = 0.f;

    scn[j] = keepf;
    __syncthreads();
    for (int off = 1; off < 1024; off <<= 1) {
        int v = (j >= off) ? scn[j - off] : 0;
        __syncthreads();
        scn[j] += v;
        __syncthreads();
    }
    int rank = scn[j] - keepf;
    if (keepf && rank < POST) {
        float* o = out + (size_t)b * POST * 5 + (size_t)rank * 5;
        o[0] = bx1; o[1] = by1; o[2] = bx2; o[3] = by2; o[4] = bscore;
    }
}

// ---------------- host launcher ----------------
extern "C" void kernel_launch(void* const* d_in, const int* in_sizes, int n_in,
                              void* d_out, int out_size) {
    const float* p[5] = {0, 0, 0, 0, 0};
    const float *convw = 0, *convb = 0, *clsw = 0, *clsb = 0, *boxw = 0, *boxb = 0;
    for (int i = 0; i < n_in; i++) {
        switch (in_sizes[i]) {
            case 33554432: p[0]  = (const float*)d_in[i]; break; // p2 (2,256,256,256)
            case 8388608:  p[1]  = (const float*)d_in[i]; break; // p3
            case 2097152:  p[2]  = (const float*)d_in[i]; break; // p4
            case 524288:   p[3]  = (const float*)d_in[i]; break; // p5
            case 131072:   p[4]  = (const float*)d_in[i]; break; // p6
            case 589824:   convw = (const float*)d_in[i]; break; // (256,256,3,3)
            case 256:      convb = (const float*)d_in[i]; break;
            case 768:      clsw  = (const float*)d_in[i]; break; // (3,256)
            case 3:        clsb  = (const float*)d_in[i]; break;
            case 3072:     boxw  = (const float*)d_in[i]; break; // (12,256)
            case 12:       boxb  = (const float*)d_in[i]; break;
        }
    }

    const int    Hs[5]      = {256, 128, 64, 32, 16};
    const int    strides[5] = {4, 8, 16, 32, 64};
    const float  sizes[5]   = {32.f, 64.f, 128.f, 256.f, 512.f};
    const int    offs[5]    = {0, 196608, 245760, 258048, 261120};
    const size_t xoffs[5]   = {0, 33554432, 41943040, 44040192, 44564480};

    static bool attr_set = false;
    if (!attr_set) {
        cudaFuncSetAttribute(conv3x3_relu_kernel,
                             cudaFuncAttributeMaxDynamicSharedMemorySize, CONV_SMEM);
        attr_set = true;
    }

    float* xbase;
    cudaGetSymbolAddress((void**)&xbase, g_x);
    float* wtbase;
    cudaGetSymbolAddress((void**)&wtbase, g_wt);

    auto conv = [&](int l) {
        int H = Hs[l], W = Hs[l];
        dim3 grid((W + 63) / 64, H / 2, 4);
        conv3x3_relu_kernel<<<grid, 256, CONV_SMEM>>>(p[l], wtbase, convb,
                                                      xbase + xoffs[l], H, W);
    };
    auto head = [&](int l) {
        int H = Hs[l], W = Hs[l];
        int HW = H * W;
        dim3 g2((HW + 255) / 256, 2);
        head_decode_kernel<<<g2, 256>>>(clsw, clsb, boxw, boxb,
                                        xbase + xoffs[l], H, W,
                                        strides[l], sizes[l], offs[l]);
    };

    wtrans_kernel<<<(589824 + 255) / 256, 256>>>(convw, wtbase);   // 0

    // keep big convs in the ncu capture window (observed to land ~idx 3-5)
    conv(4);      // 1: conv p6
    conv(3);      // 2: conv p5
    conv(2);      // 3: conv p4
    conv(0);      // 4: conv p2   <-- profile target
    conv(1);      // 5: conv p3   <-- profile target (hedge)
    head(4);      // 6
    head(3);      // 7
    head(2);      // 8
    head(0);      // 9
    head(1);      // 10

    zero_hist_kernel<<<512, 256>>>();
    hist_hi_kernel<<<1024, 256>>>();
    scan_hi_kernel<<<2, 1024>>>();
    zero_hist_kernel<<<512, 256>>>();
    hist_lo_kernel<<<1024, 256>>>();
    scan_lo_kernel<<<2, 1024>>>();
    compact_kernel<<<1024, 256>>>();
    sort_topk_kernel<<<2, 1024>>>();
    nms_out_kernel<<<2, 1024>>>((float*)d_out);
}

// round 10
// speedup vs baseline: 1.2792x; 1.0270x over previous
#include <cuda_runtime.h>
#include <cstdint>

#define NA 261888
#define TOPK 1000
#define POST 300

// ---------------- static scratch (no allocations allowed) ----------------
__device__ float              g_x[(size_t)44695552]; // per-level conv outputs
__device__ float              g_wt[589824];          // transformed conv weights
__device__ float              g_scores[2 * NA];
__device__ float4             g_boxes[2 * NA];
__device__ unsigned           g_hist[2][65536];
__device__ unsigned           g_selHi[2];
__device__ unsigned           g_above[2];
__device__ unsigned           g_T[2];
__device__ int                g_candCnt[2];
__device__ unsigned long long g_cand[2][2048];
__device__ float              g_ts[2][1024];
__device__ float4             g_tb[2][1024];

// ---------------- f32x2 packed-FMA helpers (Blackwell) ----------------
__device__ __forceinline__ unsigned long long pack_dup(float v) {
    unsigned long long r;
    unsigned u = __float_as_uint(v);
    asm("mov.b64 %0, {%1, %1};" : "=l"(r) : "r"(u));
    return r;
}
__device__ __forceinline__ void fma2(unsigned long long& acc,
                                     unsigned long long a,
                                     unsigned long long b) {
    asm("fma.rn.f32x2 %0, %1, %2, %0;" : "+l"(acc) : "l"(a), "l"(b));
}
__device__ __forceinline__ void unpack2(unsigned long long v, float& lo, float& hi) {
    unsigned a, b;
    asm("mov.b64 {%0, %1}, %2;" : "=r"(a), "=r"(b) : "l"(v));
    lo = __uint_as_float(a);
    hi = __uint_as_float(b);
}

// ---------------- XLA-exact sigmoid: 0.5 + 0.5*fast_tanh(0.5*x) ----------------
__device__ __forceinline__ float xla_fast_tanh(float x) {
    const float kBound = 7.90531110763549805f;
    float xc = fminf(fmaxf(x, -kBound), kBound);
    float x2 = __fmul_rn(xc, xc);
    float n = __fadd_rn(__fmul_rn(x2, -2.76076847742355e-16f), 2.00018790482477e-13f);
    n = __fadd_rn(__fmul_rn(x2, n), -8.60467152213735e-11f);
    n = __fadd_rn(__fmul_rn(x2, n),  5.12229709037114e-08f);
    n = __fadd_rn(__fmul_rn(x2, n),  1.48572235717979e-05f);
    n = __fadd_rn(__fmul_rn(x2, n),  6.37261928875436e-04f);
    n = __fadd_rn(__fmul_rn(x2, n),  4.89352455891786e-03f);
    n = __fmul_rn(xc, n);
    float d = __fadd_rn(__fmul_rn(x2, 1.19825839466702e-06f), 1.18534705686654e-04f);
    d = __fadd_rn(__fmul_rn(x2, d), 2.26843463243900e-03f);
    d = __fadd_rn(__fmul_rn(x2, d), 4.89352518554385e-03f);
    float t = __fdiv_rn(n, d);
    return (fabsf(x) < 0.0004f) ? x : t;
}
__device__ __forceinline__ float xla_sigmoid(float l) {
    float t = xla_fast_tanh(__fmul_rn(0.5f, l));
    return __fadd_rn(0.5f, __fmul_rn(0.5f, t));
}

// ---------------- weight transform: w[oc][ic][3][3] -> wt[g128][ic][k][ocl] ----------------
__global__ void wtrans_kernel(const float* __restrict__ w, float* __restrict__ wt) {
    int i = blockIdx.x * 256 + threadIdx.x;
    if (i >= 589824) return;
    int g   = i / 294912;
    int rem = i % 294912;
    int ic  = rem / 1152;
    int r2  = rem % 1152;
    int k   = r2 / 128;
    int ocl = r2 % 128;
    wt[i] = w[((size_t)(g * 128 + ocl) * 256 + ic) * 9 + k];
}

// ---------------- conv 3x3 (256->256) + bias + relu, templated oc tile ----------------
// Tile: 2 rows x 64 cols x (16*NOP) oc, 256 threads. Thread (tx,ty): pixels
// (y0+{0,1}, x0+{tx,tx+32}), oc = ocb + 2*NOP*ty + 2*op (op < NOP).
// Per-output FMA chain order (ic asc, ky asc, kx asc) identical to rounds
// 4-9 -> bitwise-identical output for any NOP.
template<int NOP>
__device__ __forceinline__ void conv_k_step(unsigned long long (&acc2)[NOP][4],
                                            const float* wk,
                                            unsigned long long a0, unsigned long long b0,
                                            unsigned long long a1, unsigned long long b1) {
#pragma unroll
    for (int m = 0; m < NOP / 2; m++) {
        ulonglong2 wv = *reinterpret_cast<const ulonglong2*>(wk + 4 * m);
        fma2(acc2[2 * m][0],     a0, wv.x);
        fma2(acc2[2 * m][1],     b0, wv.x);
        fma2(acc2[2 * m][2],     a1, wv.x);
        fma2(acc2[2 * m][3],     b1, wv.x);
        fma2(acc2[2 * m + 1][0], a0, wv.y);
        fma2(acc2[2 * m + 1][1], b0, wv.y);
        fma2(acc2[2 * m + 1][2], a1, wv.y);
        fma2(acc2[2 * m + 1][3], b1, wv.y);
    }
}

template<int NOP, int MINC>
__global__ void __launch_bounds__(256, MINC)
conv_t(const float* __restrict__ in,
       const float* __restrict__ wt,
       const float* __restrict__ bias,
       float* __restrict__ xout,
       int H, int W) {
    constexpr int OCPB = 16 * NOP;          // oc per block
    constexpr int NG   = 256 / OCPB;        // oc groups
    constexpr int W4   = 4 * NOP;           // float4s per [ic][k] row in smem

    extern __shared__ char smemraw[];
    float* s_w = reinterpret_cast<float*>(smemraw);                       // [8][9][OCPB]
    unsigned long long* s_in2 =
        reinterpret_cast<unsigned long long*>(smemraw + 8 * 9 * OCPB * 4); // [8][4][66]

    const int tx  = threadIdx.x & 31;
    const int ty  = threadIdx.x >> 5;
    const int x0  = blockIdx.x * 64;
    const int y0  = blockIdx.y * 2;
    const int b   = blockIdx.z / NG;
    const int ocb = (blockIdx.z % NG) * OCPB;

    unsigned long long acc2[NOP][4];
#pragma unroll
    for (int i = 0; i < NOP; i++)
#pragma unroll
        for (int j = 0; j < 4; j++) acc2[i][j] = 0ULL;

    const float* inB = in + (size_t)b * 256 * H * W;
    // base of this block's oc columns inside the g128 weight layout (float4 units)
    const float4* wsrc4 = reinterpret_cast<const float4*>(wt)
                        + (size_t)(ocb / 128) * 73728 + (ocb % 128) / 4;

    for (int icb = 0; icb < 256; icb += 8) {
        // ---- input staging: warp ty stages ic = ty (division-free) ----
        {
            const float* src = inB + (size_t)(icb + ty) * H * W;
#pragma unroll
            for (int r = 0; r < 4; r++) {
                int yy = y0 + r - 1;
                bool yok = (yy >= 0 && yy < H);
                const float* row = src + (size_t)yy * W;
                int xxA = x0 + tx - 1;
                int xxB = x0 + tx + 31;
                float vA = (yok && xxA >= 0 && xxA < W) ? row[xxA] : 0.f;
                float vB = (yok && xxB < W) ? row[xxB] : 0.f;
                s_in2[ty * 264 + r * 66 + tx]      = pack_dup(vA);
                s_in2[ty * 264 + r * 66 + tx + 32] = pack_dup(vB);
                if (tx < 2) {
                    int xxC = x0 + tx + 63;
                    float vC = (yok && xxC < W) ? row[xxC] : 0.f;
                    s_in2[ty * 264 + r * 66 + tx + 64] = pack_dup(vC);
                }
            }
        }
        // ---- weight staging: float4 copy (strided rows for NOP<8) ----
        {
            float4* dst4 = reinterpret_cast<float4*>(s_w);
            for (int e = threadIdx.x; e < 72 * W4; e += 256) {
                int ic  = e / (9 * W4);
                int rem = e - ic * 9 * W4;
                int k   = rem / W4;
                int f4  = rem - k * W4;
                dst4[e] = wsrc4[(size_t)(icb + ic) * 288 + k * 32 + f4];
            }
        }
        __syncthreads();

#pragma unroll
        for (int ic = 0; ic < 8; ic++) {
            const unsigned long long* bi = s_in2 + ic * 264;
            const float* wk = s_w + ic * 9 * OCPB + 2 * NOP * ty;

            unsigned long long A0[3], B0[3], A1[3], B1[3];
            unsigned long long A2[3], B2[3], A3[3], B3[3];
#pragma unroll
            for (int c = 0; c < 3; c++) {
                A0[c] = bi[c + tx];           B0[c] = bi[c + tx + 32];
                A1[c] = bi[66 + c + tx];      B1[c] = bi[66 + c + tx + 32];
            }
#pragma unroll
            for (int kx = 0; kx < 3; kx++)
                conv_k_step<NOP>(acc2, wk + kx * OCPB, A0[kx], B0[kx], A1[kx], B1[kx]);
#pragma unroll
            for (int c = 0; c < 3; c++) {
                A2[c] = bi[132 + c + tx];     B2[c] = bi[132 + c + tx + 32];
            }
#pragma unroll
            for (int kx = 0; kx < 3; kx++)
                conv_k_step<NOP>(acc2, wk + (3 + kx) * OCPB, A1[kx], B1[kx], A2[kx], B2[kx]);
#pragma unroll
            for (int c = 0; c < 3; c++) {
                A3[c] = bi[198 + c + tx];     B3[c] = bi[198 + c + tx + 32];
            }
#pragma unroll
            for (int kx = 0; kx < 3; kx++)
                conv_k_step<NOP>(acc2, wk + (6 + kx) * OCPB, A2[kx], B2[kx], A3[kx], B3[kx]);
        }
        __syncthreads();
    }

#pragma unroll
    for (int op = 0; op < NOP; op++) {
        const int ocl = ocb + 2 * NOP * ty + 2 * op;
        const float bv0 = bias[ocl];
        const float bv1 = bias[ocl + 1];
        float* out0 = xout + (size_t)(b * 256 + ocl) * H * W;
        float* out1 = out0 + (size_t)H * W;
#pragma unroll
        for (int q = 0; q < 4; q++) {
            float v0, v1;
            unpack2(acc2[op][q], v0, v1);
            int y = y0 + (q >> 1);
            int x = (q & 1) ? (x0 + 32 + tx) : (x0 + tx);
            if (x < W) {
                out0[(size_t)y * W + x] = fmaxf(__fadd_rn(v0, bv0), 0.f);
                out1[(size_t)y * W + x] = fmaxf(__fadd_rn(v1, bv1), 0.f);
            }
        }
    }
}

#define CONV_SMEM_BIG   (8 * 9 * 128 * 4 + 16896)   // 53760
#define CONV_SMEM_SMALL (8 * 9 * 32 * 4 + 16896)    // 26112

// ---------------- 1x1 heads + anchor decode + sigmoid + mask ----------------
// f32x2 accumulators with transposed weight staging; per-output c-ascending
// chain order preserved lane-wise -> bitwise identical to rounds 4-9.
__global__ void head_decode_kernel(const float* __restrict__ clsw, const float* __restrict__ clsb,
                                   const float* __restrict__ boxw, const float* __restrict__ boxb,
                                   const float* __restrict__ xin,
                                   int H, int W, int stride, float asize, int lvl_off) {
    __shared__ float s_cwt[256][4];    // [c][a], a<3 used; row 16B
    __shared__ float s_bwt[256][12];   // [c][j]; row 48B, 8B-aligned pairs

    for (int e = threadIdx.x; e < 3 * 256; e += blockDim.x) {
        int a = e >> 8, c = e & 255;
        s_cwt[c][a] = clsw[e];
    }
    for (int e = threadIdx.x; e < 12 * 256; e += blockDim.x) {
        int j = e >> 8, c = e & 255;
        s_bwt[c][j] = boxw[e];
    }
    __syncthreads();

    int pix = blockIdx.x * blockDim.x + threadIdx.x;
    int b   = blockIdx.y;
    int HW  = H * W;
    if (pix >= HW) return;

    const float* xp = xin + (size_t)b * 256 * HW + pix;
    unsigned long long o01 = 0ULL;
    float o2 = 0.f;
    unsigned long long dd[6];
#pragma unroll
    for (int m = 0; m < 6; m++) dd[m] = 0ULL;

#pragma unroll 4
    for (int c = 0; c < 256; c++) {
        float v = xp[(size_t)c * HW];
        unsigned long long v2 = pack_dup(v);
        fma2(o01, v2, *reinterpret_cast<const unsigned long long*>(&s_cwt[c][0]));
        o2 += v * s_cwt[c][2];
        const float* wr = s_bwt[c];
#pragma unroll
        for (int m = 0; m < 6; m++)
            fma2(dd[m], v2, *reinterpret_cast<const unsigned long long*>(wr + 2 * m));
    }

    float o[3];
    unpack2(o01, o[0], o[1]);
    o[2] = o2;
    float d[12];
#pragma unroll
    for (int m = 0; m < 6; m++) unpack2(dd[m], d[2 * m], d[2 * m + 1]);

#pragma unroll
    for (int a = 0; a < 3; a++) o[a] = __fadd_rn(o[a], clsb[a]);
#pragma unroll
    for (int j = 0; j < 12; j++) d[j] = __fadd_rn(d[j], boxb[j]);

    int yy = pix / W, xx = pix % W;
    float xs = (float)(xx * stride), ys = (float)(yy * stride);
    const float ratios[3] = {0.5f, 1.0f, 2.0f};
#pragma unroll
    for (int a = 0; a < 3; a++) {
        float s  = sqrtf(ratios[a]);
        float hh = __fmul_rn(asize, s);
        float ww = __fdiv_rn(asize, s);
        float ax1 = __fadd_rn(xs, -0.5f * ww);
        float ax2 = __fadd_rn(xs,  0.5f * ww);
        float ay1 = __fadd_rn(ys, -0.5f * hh);
        float ay2 = __fadd_rn(ys,  0.5f * hh);
        float aw = __fsub_rn(ax2, ax1);
        float ah = __fsub_rn(ay2, ay1);
        float ax = __fadd_rn(ax1, 0.5f * aw);
        float ay = __fadd_rn(ay1, 0.5f * ah);
        float dx = d[4 * a], dy = d[4 * a + 1], dw = d[4 * a + 2], dh = d[4 * a + 3];
        float cx = __fadd_rn(__fmul_rn(dx, aw), ax);
        float cy = __fadd_rn(__fmul_rn(dy, ah), ay);
        float pw = __fmul_rn(expf(dw), aw);
        float ph = __fmul_rn(expf(dh), ah);
        float x1 = __fsub_rn(cx, 0.5f * pw);
        float y1 = __fsub_rn(cy, 0.5f * ph);
        float x2 = __fadd_rn(cx, 0.5f * pw);
        float y2 = __fadd_rn(cy, 0.5f * ph);
        x1 = fminf(fmaxf(x1, 0.f), 1024.f);
        y1 = fminf(fmaxf(y1, 0.f), 1024.f);
        x2 = fminf(fmaxf(x2, 0.f), 1024.f);
        y2 = fminf(fmaxf(y2, 0.f), 1024.f);
        float ws = __fsub_rn(x2, x1), hs = __fsub_rn(y2, y1);
        bool valid = (ws >= 1.0f) && (hs >= 1.0f);
        float sc = xla_sigmoid(o[a]);
        float masked = valid ? sc : -1e9f;
        int aidx = lvl_off + pix * 3 + a;
        g_scores[(size_t)b * NA + aidx] = masked;
        g_boxes[(size_t)b * NA + aidx] = make_float4(x1, y1, x2, y2);
    }
}

// ---------------- top-k via 2-pass 16-bit radix select ----------------
__device__ __forceinline__ unsigned f2u(float f) {
    unsigned u = __float_as_uint(f);
    return (u & 0x80000000u) ? ~u : (u | 0x80000000u);
}

__global__ void zero_hist_kernel() {
    int i = blockIdx.x * blockDim.x + threadIdx.x;
    if (i < 2 * 65536) (&g_hist[0][0])[i] = 0u;
}

__global__ void hist_hi_kernel() {
    for (int i = blockIdx.x * blockDim.x + threadIdx.x; i < 2 * NA; i += gridDim.x * blockDim.x) {
        int b = i / NA;
        unsigned k = f2u(g_scores[i]);
        atomicAdd(&g_hist[b][k >> 16], 1u);
    }
}

__global__ void scan_hi_kernel() {
    int b = blockIdx.x, tid = threadIdx.x;
    __shared__ unsigned ssum[1024];
    unsigned tsum = 0;
    int base = tid * 64;
    for (int i = 0; i < 64; i++) tsum += g_hist[b][base + i];
    ssum[tid] = tsum;
    __syncthreads();
    for (int off = 1; off < 1024; off <<= 1) {
        unsigned v = (tid + off < 1024) ? ssum[tid + off] : 0u;
        __syncthreads();
        ssum[tid] += v;
        __syncthreads();
    }
    unsigned above = ssum[tid] - tsum;
    if (above < TOPK && above + tsum >= TOPK) {
        unsigned acc = above;
        for (int i = 63; i >= 0; i--) {
            unsigned c = g_hist[b][base + i];
            if (acc + c >= TOPK) { g_selHi[b] = (unsigned)(base + i); g_above[b] = acc; break; }
            acc += c;
        }
    }
}

__global__ void hist_lo_kernel() {
    for (int i = blockIdx.x * blockDim.x + threadIdx.x; i < 2 * NA; i += gridDim.x * blockDim.x) {
        int b = i / NA;
        unsigned k = f2u(g_scores[i]);
        if ((k >> 16) == g_selHi[b]) atomicAdd(&g_hist[b][k & 0xFFFFu], 1u);
    }
}

__global__ void scan_lo_kernel() {
    int b = blockIdx.x, tid = threadIdx.x;
    unsigned Kp = TOPK - g_above[b];
    __shared__ unsigned ssum[1024];
    unsigned tsum = 0;
    int base = tid * 64;
    for (int i = 0; i < 64; i++) tsum += g_hist[b][base + i];
    ssum[tid] = tsum;
    __syncthreads();
    for (int off = 1; off < 1024; off <<= 1) {
        unsigned v = (tid + off < 1024) ? ssum[tid + off] : 0u;
        __syncthreads();
        ssum[tid] += v;
        __syncthreads();
    }
    unsigned above = ssum[tid] - tsum;
    if (above < Kp && above + tsum >= Kp) {
        unsigned acc = above;
        for (int i = 63; i >= 0; i--) {
            unsigned c = g_hist[b][base + i];
            if (acc + c >= Kp) {
                g_T[b] = (g_selHi[b] << 16) | (unsigned)(base + i);
                break;
            }
            acc += c;
        }
    }
    if (tid == 0) g_candCnt[b] = 0;
}

__global__ void compact_kernel() {
    for (int i = blockIdx.x * blockDim.x + threadIdx.x; i < 2 * NA; i += gridDim.x * blockDim.x) {
        int b = i / NA;
        unsigned k = f2u(g_scores[i]);
        if (k >= g_T[b]) {
            int p = atomicAdd(&g_candCnt[b], 1);
            if (p < 2048) {
                unsigned idx = (unsigned)(i - b * NA);
                g_cand[b][p] = ((unsigned long long)k << 32) | (unsigned long long)(~idx);
            }
        }
    }
}

// Bitonic sort of <=2048 candidates, composite key (score desc, index asc)
__global__ void sort_topk_kernel() {
    int b = blockIdx.x, tid = threadIdx.x;
    __shared__ unsigned long long s[2048];
    int n = g_candCnt[b];
    if (n > 2048) n = 2048;
    for (int t = tid; t < 2048; t += 1024) s[t] = (t < n) ? g_cand[b][t] : 0ULL;
    __syncthreads();
    for (int k = 2; k <= 2048; k <<= 1) {
        for (int j = k >> 1; j > 0; j >>= 1) {
            int i = ((tid & ~(j - 1)) << 1) | (tid & (j - 1));
            int p = i | j;
            bool desc = ((i & k) == 0);
            unsigned long long a = s[i], c = s[p];
            if (desc ? (a < c) : (a > c)) { s[i] = c; s[p] = a; }
            __syncthreads();
        }
    }
    if (tid < TOPK) {
        unsigned long long v = s[tid];
        if (v != 0ULL) {
            unsigned idx = ~(unsigned)(v & 0xFFFFFFFFull);
            g_ts[b][tid] = g_scores[(size_t)b * NA + idx];
            g_tb[b][tid] = g_boxes[(size_t)b * NA + idx];
        } else {
            g_ts[b][tid] = -1e9f;
            g_tb[b][tid] = make_float4(0.f, 0.f, 0.f, 0.f);
        }
    }
}

// ---------------- greedy NMS + compaction to (300,5) ----------------
__global__ void nms_out_kernel(float* __restrict__ out) {
    int b = blockIdx.x, j = threadIdx.x;
    __shared__ float sx1[TOPK], sy1[TOPK], sx2[TOPK], sy2[TOPK], sar[TOPK];
    __shared__ int   supp[TOPK];
    __shared__ int   scn[1024];

    float bx1 = 0.f, by1 = 0.f, bx2 = 0.f, by2 = 0.f, barea = 0.f, bscore = -1e9f;
    if (j < TOPK) {
        float4 bb = g_tb[b][j];
        bx1 = bb.x; by1 = bb.y; bx2 = bb.z; by2 = bb.w;
        barea = __fmul_rn(__fsub_rn(bx2, bx1), __fsub_rn(by2, by1));
        bscore = g_ts[b][j];
        sx1[j] = bx1; sy1[j] = by1; sx2[j] = bx2; sy2[j] = by2; sar[j] = barea;
        supp[j] = 0;
    }
    __syncthreads();

    for (int i = 0; i < TOPK; i++) {
        if (!supp[i]) {
            if (j > i && j < TOPK && !supp[j]) {
                float xx1 = fmaxf(sx1[i], bx1);
                float yy1 = fmaxf(sy1[i], by1);
                float xx2 = fminf(sx2[i], bx2);
                float yy2 = fminf(sy2[i], by2);
                float inter = __fmul_rn(fmaxf(__fsub_rn(xx2, xx1), 0.f),
                                        fmaxf(__fsub_rn(yy2, yy1), 0.f));
                float den = __fadd_rn(__fsub_rn(__fadd_rn(sar[i], barea), inter), 1e-9f);
                float iou = __fdiv_rn(inter, den);
                if (iou > 0.7f) supp[j] = 1;
            }
            __syncthreads();
        }
    }

    int keepf = (j < TOPK && !supp[j] && bscore > -1e8f) ? 1 : 0;

    for (int t = j; t < POST * 5; t += 1024) out[(size_t)b * POST * 5 + t] = 0.f;

    scn[j] = keepf;
    __syncthreads();
    for (int off = 1; off < 1024; off <<= 1) {
        int v = (j >= off) ? scn[j - off] : 0;
        __syncthreads();
        scn[j] += v;
        __syncthreads();
    }
    int rank = scn[j] - keepf;
    if (keepf && rank < POST) {
        float* o = out + (size_t)b * POST * 5 + (size_t)rank * 5;
        o[0] = bx1; o[1] = by1; o[2] = bx2; o[3] = by2; o[4] = bscore;
    }
}

// ---------------- host launcher ----------------
extern "C" void kernel_launch(void* const* d_in, const int* in_sizes, int n_in,
                              void* d_out, int out_size) {
    const float* p[5] = {0, 0, 0, 0, 0};
    const float *convw = 0, *convb = 0, *clsw = 0, *clsb = 0, *boxw = 0, *boxb = 0;
    for (int i = 0; i < n_in; i++) {
        switch (in_sizes[i]) {
            case 33554432: p[0]  = (const float*)d_in[i]; break; // p2 (2,256,256,256)
            case 8388608:  p[1]  = (const float*)d_in[i]; break; // p3
            case 2097152:  p[2]  = (const float*)d_in[i]; break; // p4
            case 524288:   p[3]  = (const float*)d_in[i]; break; // p5
            case 131072:   p[4]  = (const float*)d_in[i]; break; // p6
            case 589824:   convw = (const float*)d_in[i]; break; // (256,256,3,3)
            case 256:      convb = (const float*)d_in[i]; break;
            case 768:      clsw  = (const float*)d_in[i]; break; // (3,256)
            case 3:        clsb  = (const float*)d_in[i]; break;
            case 3072:     boxw  = (const float*)d_in[i]; break; // (12,256)
            case 12:       boxb  = (const float*)d_in[i]; break;
        }
    }

    const int    Hs[5]      = {256, 128, 64, 32, 16};
    const int    strides[5] = {4, 8, 16, 32, 64};
    const float  sizes[5]   = {32.f, 64.f, 128.f, 256.f, 512.f};
    const int    offs[5]    = {0, 196608, 245760, 258048, 261120};
    const size_t xoffs[5]   = {0, 33554432, 41943040, 44040192, 44564480};

    static bool attr_set = false;
    if (!attr_set) {
        cudaFuncSetAttribute(conv_t<8, 2>,
                             cudaFuncAttributeMaxDynamicSharedMemorySize, CONV_SMEM_BIG);
        attr_set = true;
    }

    float* xbase;
    cudaGetSymbolAddress((void**)&xbase, g_x);
    float* wtbase;
    cudaGetSymbolAddress((void**)&wtbase, g_wt);

    auto conv = [&](int l) {
        int H = Hs[l], W = Hs[l];
        if (l <= 1) {  // p2, p3: 128-oc tile
            dim3 grid((W + 63) / 64, H / 2, 4);
            conv_t<8, 2><<<grid, 256, CONV_SMEM_BIG>>>(p[l], wtbase, convb,
                                                       xbase + xoffs[l], H, W);
        } else {       // p4, p5, p6: 32-oc tile for parallelism
            dim3 grid((W + 63) / 64, H / 2, 16);
            conv_t<2, 3><<<grid, 256, CONV_SMEM_SMALL>>>(p[l], wtbase, convb,
                                                         xbase + xoffs[l], H, W);
        }
    };
    auto head = [&](int l) {
        int H = Hs[l], W = Hs[l];
        int HW = H * W;
        dim3 g2((HW + 255) / 256, 2);
        head_decode_kernel<<<g2, 256>>>(clsw, clsb, boxw, boxb,
                                        xbase + xoffs[l], H, W,
                                        strides[l], sizes[l], offs[l]);
    };

    wtrans_kernel<<<(589824 + 255) / 256, 256>>>(convw, wtbase);   // 0

    conv(4);      // 1: conv p6 (small tile)
    conv(3);      // 2: conv p5 (small tile)
    conv(0);      // 3: conv p2   <-- profile target (idx 3)
    conv(2);      // 4: conv p4 (small tile)
    conv(1);      // 5: conv p3
    head(4);      // 6
    head(3);      // 7
    head(2);      // 8
    head(0);      // 9
    head(1);      // 10

    zero_hist_kernel<<<512, 256>>>();
    hist_hi_kernel<<<1024, 256>>>();
    scan_hi_kernel<<<2, 1024>>>();
    zero_hist_kernel<<<512, 256>>>();
    hist_lo_kernel<<<1024, 256>>>();
    scan_lo_kernel<<<2, 1024>>>();
    compact_kernel<<<1024, 256>>>();
    sort_topk_kernel<<<2, 1024>>>();
    nms_out_kernel<<<2, 1024>>>((float*)d_out);
}